// round 8
// baseline (speedup 1.0000x reference)
#include <cuda_runtime.h>
#include <cuda_fp16.h>
#include <cstdint>

#define HN       128
#define BATCH    1024
#define SEQT     512
#define CL       8            // CTAs per cluster
#define MROWS    64           // batch rows per cluster
#define NTHREADS 128

#define SAW      132          // A-tile row stride in 32-bit words (264 fp16 = 528 B)

// ---- shared memory layout (32-bit word offsets) ----
#define OF_A     0                       // A tile [64][264 fp16] = 8448 words
#define OF_B1    (64 * SAW)              // layer-1 B frags: 4096 words (16 KB)
#define OF_B2    (OF_B1 + 4096)          // layer-2 B frags: 8192 words (32 KB)
#define OF_WX    (OF_B2 + 8192)          // Wih1 slice   [64] floats
#define OF_BB1   (OF_WX + 64)            // bih1+bhh1    [64] floats
#define OF_BB2   (OF_BB1 + 64)           // bih2+bhh2    [64] floats
#define OF_MBAR  (OF_BB2 + 64)           // cluster exchange mbarrier (u64, 8B aligned)
#define SMEM_WORDS (OF_MBAR + 2)
#define SMEM_BYTES (SMEM_WORDS * 4)

// ---- device scratch (allocation-free) ----
__device__ float    g_xT[SEQT * BATCH];      // x transposed to [T, B]
__device__ uint32_t g_h[2][BATCH * 128];     // double-buffered: per row 128 words = [h1 | h2] fp16

// ======================= helpers =======================
__device__ __forceinline__ uint32_t smem_u32(const void* p) {
    uint32_t a;
    asm("{ .reg .u64 t; cvta.to.shared.u64 t, %1; cvt.u32.u64 %0, t; }" : "=r"(a) : "l"(p));
    return a;
}
#define CLUSTER_ARRIVE() asm volatile("barrier.cluster.arrive.aligned;" ::: "memory")
#define CLUSTER_WAIT()   asm volatile("barrier.cluster.wait.aligned;" ::: "memory")

__device__ __forceinline__ void mmaf16(float* d, const uint32_t* a, uint32_t b0, uint32_t b1) {
    asm volatile(
        "mma.sync.aligned.m16n8k16.row.col.f32.f16.f16.f32 "
        "{%0,%1,%2,%3}, {%4,%5,%6,%7}, {%8,%9}, {%0,%1,%2,%3};"
        : "+f"(d[0]), "+f"(d[1]), "+f"(d[2]), "+f"(d[3])
        : "r"(a[0]), "r"(a[1]), "r"(a[2]), "r"(a[3]), "r"(b0), "r"(b1));
}
__device__ __forceinline__ void ldmA(uint32_t* r, uint32_t addr) {
    asm volatile("ldmatrix.sync.aligned.m8n8.x4.shared.b16 {%0,%1,%2,%3}, [%4];"
                 : "=r"(r[0]), "=r"(r[1]), "=r"(r[2]), "=r"(r[3]) : "r"(addr));
}
// MUFU tanh.approx: R6 measured +6e-7 rel_err vs exact path -> use everywhere
__device__ __forceinline__ float tanha(float x) {
    float y; asm("tanh.approx.f32 %0, %1;" : "=f"(y) : "f"(x)); return y;
}
__device__ __forceinline__ float sigfa(float x) {
    return fmaf(0.5f, tanha(0.5f * x), 0.5f);
}

// cluster exchange mbarrier ops
__device__ __forceinline__ void mbar_init(uint32_t mb, uint32_t count) {
    asm volatile("mbarrier.init.shared.b64 [%0], %1;" :: "r"(mb), "r"(count) : "memory");
}
__device__ __forceinline__ void mbar_arrive_all_ctas(uint32_t mb) {
#pragma unroll
    for (int c = 0; c < CL; c++) {
        uint32_t rmb;
        asm volatile("mapa.shared::cluster.u32 %0, %1, %2;" : "=r"(rmb) : "r"(mb), "r"(c));
        asm volatile("mbarrier.arrive.release.cluster.shared::cluster.b64 _, [%0];"
                     :: "r"(rmb) : "memory");
    }
}
__device__ __forceinline__ void mbar_wait_cluster(uint32_t mb, uint32_t parity) {
    asm volatile(
        "{\n\t.reg .pred P;\n\t"
        "LAB_%=:\n\t"
        "mbarrier.try_wait.parity.acquire.cluster.shared::cta.b64 P, [%0], %1, 0x989680;\n\t"
        "@P bra.uni DONE_%=;\n\t"
        "bra.uni LAB_%=;\n\t"
        "DONE_%=:\n\t}"
        :: "r"(mb), "r"(parity) : "memory");
}

// ======================= kernels =======================
__global__ void xT_kernel(const float* __restrict__ x) {
    int i = blockIdx.x * blockDim.x + threadIdx.x;   // i = t*1024 + b (coalesced writes)
    if (i < BATCH * SEQT) {
        int tt = i >> 10, b = i & 1023;
        g_xT[i] = x[b * SEQT + tt];
    }
}

extern "C" __global__ void __launch_bounds__(NTHREADS, 1) __cluster_dims__(CL, 1, 1)
lstm2_kernel(const float* __restrict__ Wih1, const float* __restrict__ Whh1,
             const float* __restrict__ bih1, const float* __restrict__ bhh1,
             const float* __restrict__ Wih2, const float* __restrict__ Whh2,
             const float* __restrict__ bih2, const float* __restrict__ bhh2,
             const float* __restrict__ Wl,   const float* __restrict__ bl,
             float* __restrict__ out)
{
    extern __shared__ uint32_t sm[];
    const int tid  = threadIdx.x;
    const int lane = tid & 31;
    const int wid  = tid >> 5;
    const int g    = lane >> 2;
    const int tq   = lane & 3;
    const int mhalf = wid >> 1, qh = wid & 1;
    const int mbase = mhalf * 32;
    const int rank = blockIdx.x & (CL - 1);
    const int b0   = (blockIdx.x / CL) * MROWS;

    float* WX  = (float*)(sm + OF_WX);
    float* BB1 = (float*)(sm + OF_BB1);
    float* BB2 = (float*)(sm + OF_BB2);
    const uint32_t mbaddr = smem_u32(sm) + OF_MBAR * 4;

    // ---- pack weight slices into fp16 mma-fragment order ----
    // Consumption: uint4 U = ((q2*KTP + ktp)*2 + p)*32 + lane  -> word = 4*U + j
    // decode: j = idx&3, lane = (idx>>2)&31, p = (idx>>7)&1, ktp next, q2 top.
    // Fragment: gate = p*2 + (j>>1), reg = j&1;
    // B[k][n]: k0 = ktp*16 + reg*8 + 2*(lane&3), n = q2*8 + (lane>>2)
    for (int idx = tid; idx < 4096; idx += NTHREADS) {          // layer 1 (K=128)
        int j = idx & 3, ln = (idx >> 2) & 31, p = (idx >> 7) & 1;
        int ktp = (idx >> 8) & 7, q2 = idx >> 11;
        int gate = p * 2 + (j >> 1), reg = j & 1;
        int gg = ln >> 2, ttq = ln & 3;
        int k0 = ktp * 16 + reg * 8 + 2 * ttq;
        int gr = gate * HN + rank * 16 + q2 * 8 + gg;
        __half2 hv = __floats2half2_rn(Whh1[gr * HN + k0], Whh1[gr * HN + k0 + 1]);
        sm[OF_B1 + idx] = *(uint32_t*)&hv;
    }
    for (int idx = tid; idx < 8192; idx += NTHREADS) {          // layer 2 (K=256)
        int j = idx & 3, ln = (idx >> 2) & 31, p = (idx >> 7) & 1;
        int ktp = (idx >> 8) & 15, q2 = idx >> 12;
        int gate = p * 2 + (j >> 1), reg = j & 1;
        int gg = ln >> 2, ttq = ln & 3;
        int k0 = ktp * 16 + reg * 8 + 2 * ttq;
        int gr = gate * HN + rank * 16 + q2 * 8 + gg;
        float w0 = (k0 < HN)     ? Wih2[gr * HN + k0]     : Whh2[gr * HN + k0 - HN];
        float w1 = (k0 + 1 < HN) ? Wih2[gr * HN + k0 + 1] : Whh2[gr * HN + k0 + 1 - HN];
        __half2 hv = __floats2half2_rn(w0, w1);
        sm[OF_B2 + idx] = *(uint32_t*)&hv;
    }
    if (tid < 64) {
        int gt = tid >> 4, q = tid & 15;
        int gr = gt * HN + rank * 16 + q;
        WX[tid]  = Wih1[gr];
        BB1[tid] = bih1[gr] + bhh1[gr];
        BB2[tid] = bih2[gr] + bhh2[gr];
    }
    for (int i = tid; i < 64 * SAW; i += NTHREADS) sm[OF_A + i] = 0u;   // h1=h2=0
    if (tid == 0) mbar_init(mbaddr, CL);
    __syncthreads();
    // publish mbarrier init to peers before any remote arrive can land
    CLUSTER_ARRIVE();
    CLUSTER_WAIT();

    // per-thread rows and addresses
    int rows[4];
#pragma unroll
    for (int mt = 0; mt < 2; mt++)
#pragma unroll
        for (int rr = 0; rr < 2; rr++)
            rows[mt * 2 + rr] = mbase + mt * 16 + g + 8 * rr;

    const uint32_t sbA = smem_u32(sm) + OF_A * 4;
    uint32_t lmaddr[2];   // ldmatrix byte address per mt (ktp col added in loop)
#pragma unroll
    for (int mt = 0; mt < 2; mt++) {
        int row_in = mbase + mt * 16 + (lane & 7) + ((lane >> 3) & 1) * 8;
        lmaddr[mt] = sbA + (uint32_t)row_in * 528u + ((lane >> 4) & 1) * 16u;
    }
    const uint4* Bq1 = (const uint4*)(sm + OF_B1);
    const uint4* Bq2 = (const uint4*)(sm + OF_B2);

    float c1[8], c2[8];
#pragma unroll
    for (int i = 0; i < 8; i++) { c1[i] = 0.f; c2[i] = 0.f; }

    for (int n = 0; n <= SEQT; n++) {
        uint32_t* ghw = g_h[n & 1];     // this iteration's exchange buffer

        // prefetch x(n) early (consumed after MMA)
        float xtv[4];
        if (n < SEQT) {
#pragma unroll
            for (int e = 0; e < 4; e++) xtv[e] = __ldcg(&g_xT[n * BATCH + b0 + rows[e]]);
        }

        float acc1[4][2][4], acc2[4][2][4];
#pragma unroll
        for (int a1 = 0; a1 < 4; a1++)
#pragma unroll
            for (int a2 = 0; a2 < 2; a2++)
#pragma unroll
                for (int a3 = 0; a3 < 4; a3++) { acc1[a1][a2][a3] = 0.f; acc2[a1][a2][a3] = 0.f; }

        // ---- k chunks 0..7 : A cols 0:128 = h1(n-1), feeds gates1 AND gates2 ----
#pragma unroll 2
        for (int ktp = 0; ktp < 8; ktp++) {
            uint4 b1a = Bq1[((qh * 8 + ktp) * 2 + 0) * 32 + lane];
            uint4 b1b = Bq1[((qh * 8 + ktp) * 2 + 1) * 32 + lane];
            uint4 b2a = Bq2[((qh * 16 + ktp) * 2 + 0) * 32 + lane];
            uint4 b2b = Bq2[((qh * 16 + ktp) * 2 + 1) * 32 + lane];
#pragma unroll
            for (int mt = 0; mt < 2; mt++) {
                uint32_t af[4];
                ldmA(af, lmaddr[mt] + ktp * 32u);
                mmaf16(acc1[0][mt], af, b1a.x, b1a.y);
                mmaf16(acc1[1][mt], af, b1a.z, b1a.w);
                mmaf16(acc1[2][mt], af, b1b.x, b1b.y);
                mmaf16(acc1[3][mt], af, b1b.z, b1b.w);
                mmaf16(acc2[0][mt], af, b2a.x, b2a.y);
                mmaf16(acc2[1][mt], af, b2a.z, b2a.w);
                mmaf16(acc2[2][mt], af, b2b.x, b2b.y);
                mmaf16(acc2[3][mt], af, b2b.z, b2b.w);
            }
        }
        // ---- k chunks 8..15 : A cols 128:256 = h2(n-2), gates2 only ----
#pragma unroll 2
        for (int ktp = 8; ktp < 16; ktp++) {
            uint4 b2a = Bq2[((qh * 16 + ktp) * 2 + 0) * 32 + lane];
            uint4 b2b = Bq2[((qh * 16 + ktp) * 2 + 1) * 32 + lane];
#pragma unroll
            for (int mt = 0; mt < 2; mt++) {
                uint32_t af[4];
                ldmA(af, lmaddr[mt] + ktp * 32u);
                mmaf16(acc2[0][mt], af, b2a.x, b2a.y);
                mmaf16(acc2[1][mt], af, b2a.z, b2a.w);
                mmaf16(acc2[2][mt], af, b2b.x, b2b.y);
                mmaf16(acc2[3][mt], af, b2b.z, b2b.w);
            }
        }

        // ---- epilogue 1: layer-1 cell for t=n ----
        if (n < SEQT) {
#pragma unroll
            for (int mt = 0; mt < 2; mt++)
#pragma unroll
                for (int rr = 0; rr < 2; rr++) {
                    int e = mt * 2 + rr;
                    float hv[2];
#pragma unroll
                    for (int qq = 0; qq < 2; qq++) {
                        int fr = rr * 2 + qq;
                        int qloc = qh * 8 + tq * 2 + qq;
                        float gi = acc1[0][mt][fr] + xtv[e] * WX[qloc]      + BB1[qloc];
                        float gf = acc1[1][mt][fr] + xtv[e] * WX[16 + qloc] + BB1[16 + qloc];
                        float gg = acc1[2][mt][fr] + xtv[e] * WX[32 + qloc] + BB1[32 + qloc];
                        float go = acc1[3][mt][fr] + xtv[e] * WX[48 + qloc] + BB1[48 + qloc];
                        float iv = sigfa(gi), fv = sigfa(gf), gv = tanha(gg), ov = sigfa(go);
                        int ci = e * 2 + qq;
                        c1[ci] = fv * c1[ci] + iv * gv;
                        hv[qq] = ov * tanha(c1[ci]);
                    }
                    __half2 hp = __floats2half2_rn(hv[0], hv[1]);
                    ghw[(size_t)(b0 + rows[e]) * 128 + rank * 8 + qh * 4 + tq] = *(uint32_t*)&hp;
                }
        }
        // ---- epilogue 2: layer-2 cell for t=n-1 ----
        if (n > 0) {
#pragma unroll
            for (int mt = 0; mt < 2; mt++)
#pragma unroll
                for (int rr = 0; rr < 2; rr++) {
                    int e = mt * 2 + rr;
                    float hv[2];
#pragma unroll
                    for (int qq = 0; qq < 2; qq++) {
                        int fr = rr * 2 + qq;
                        int qloc = qh * 8 + tq * 2 + qq;
                        float gi = acc2[0][mt][fr] + BB2[qloc];
                        float gf = acc2[1][mt][fr] + BB2[16 + qloc];
                        float gg = acc2[2][mt][fr] + BB2[32 + qloc];
                        float go = acc2[3][mt][fr] + BB2[48 + qloc];
                        float iv = sigfa(gi), fv = sigfa(gf), gv = tanha(gg), ov = sigfa(go);
                        int ci = e * 2 + qq;
                        c2[ci] = fv * c2[ci] + iv * gv;
                        hv[qq] = ov * tanha(c2[ci]);
                    }
                    __half2 hp = __floats2half2_rn(hv[0], hv[1]);
                    ghw[(size_t)(b0 + rows[e]) * 128 + 64 + rank * 8 + qh * 4 + tq] = *(uint32_t*)&hp;
                }
        } else {
            // h2(-1) = 0 (c2 untouched)
#pragma unroll
            for (int e = 0; e < 4; e++)
                ghw[(size_t)(b0 + rows[e]) * 128 + 64 + rank * 8 + qh * 4 + tq] = 0u;
        }

        if (n < SEQT) {
            // exchange: STGs -> intra-CTA order -> release-arrive on every CTA's mbarrier;
            // acquire-wait on own mbarrier (count = CL per phase, parity = n&1)
            __syncthreads();
            if (tid == 0) mbar_arrive_all_ctas(mbaddr);
            mbar_wait_cluster(mbaddr, n & 1);
            // gather full [h1(n) | h2(n-1)] into A tile: each thread copies a 64-word half-row
            {
                int r = tid >> 1, half = tid & 1;
                const uint4* src = (const uint4*)(ghw + (size_t)(b0 + r) * 128 + half * 64);
                uint4* dst = (uint4*)(sm + OF_A + r * SAW + half * 64);
#pragma unroll
                for (int j = 0; j < 16; j++) dst[j] = __ldcg(src + j);
            }
            __syncthreads();
        }
    }

    // ---- final linear: out[b] = h2[b,:] . Wl + bl ----
    CLUSTER_ARRIVE();
    CLUSTER_WAIT();
    if (rank == 0 && tid < MROWS) {
        const uint32_t* hr = g_h[SEQT & 1] + (size_t)(b0 + tid) * 128 + 64;
        float acc = bl[0];
#pragma unroll 16
        for (int w = 0; w < 64; w++) {
            uint32_t u = __ldcg(&hr[w]);
            float2 f = __half22float2(*(__half2*)&u);
            acc += f.x * Wl[2 * w] + f.y * Wl[2 * w + 1];
        }
        out[b0 + tid] = acc;
    }
}

// ======================= launch =======================
extern "C" void kernel_launch(void* const* d_in, const int* in_sizes, int n_in,
                              void* d_out, int out_size) {
    const float* x    = (const float*)d_in[0];
    const float* Wih1 = (const float*)d_in[1];
    const float* Whh1 = (const float*)d_in[2];
    const float* bih1 = (const float*)d_in[3];
    const float* bhh1 = (const float*)d_in[4];
    const float* Wih2 = (const float*)d_in[5];
    const float* Whh2 = (const float*)d_in[6];
    const float* bih2 = (const float*)d_in[7];
    const float* bhh2 = (const float*)d_in[8];
    const float* Wl   = (const float*)d_in[9];
    const float* bl   = (const float*)d_in[10];
    float* out = (float*)d_out;

    cudaFuncSetAttribute(lstm2_kernel, cudaFuncAttributeMaxDynamicSharedMemorySize, SMEM_BYTES);

    xT_kernel<<<(BATCH * SEQT + 255) / 256, 256>>>(x);
    lstm2_kernel<<<(BATCH / MROWS) * CL, NTHREADS, SMEM_BYTES>>>(
        Wih1, Whh1, bih1, bhh1, Wih2, Whh2, bih2, bhh2, Wl, bl, out);
}

// round 9
// speedup vs baseline: 1.1281x; 1.1281x over previous
#include <cuda_runtime.h>
#include <cuda_fp16.h>
#include <cstdint>

#define HN       128
#define BATCH    1024
#define SEQT     512
#define CL       8            // CTAs per cluster
#define MROWS    64           // batch rows per cluster
#define NTHREADS 256

#define SAW      132          // A-tile row stride in 32-bit words (264 fp16 = 528 B)

// ---- shared memory layout (32-bit word offsets) ----
#define OF_A     0                       // A tile [64][264 fp16] = 8448 words
#define OF_B1    (64 * SAW)              // layer-1 B frags: 4096 words (16 KB)
#define OF_B2    (OF_B1 + 4096)          // layer-2 B frags: 8192 words (32 KB)
#define OF_WX    (OF_B2 + 8192)          // Wih1 slice   [64] floats
#define OF_BB1   (OF_WX + 64)            // bih1+bhh1    [64] floats
#define OF_BB2   (OF_BB1 + 64)           // bih2+bhh2    [64] floats
#define SMEM_WORDS (OF_BB2 + 64)
#define SMEM_BYTES (SMEM_WORDS * 4)      // 83,712 B

// ---- device scratch (allocation-free) ----
__device__ float    g_xT[SEQT * BATCH];      // x transposed to [T, B]
__device__ uint32_t g_h[2][BATCH * 128];     // double-buffered: per row 128 words = [h1 | h2] fp16

// ======================= helpers =======================
__device__ __forceinline__ uint32_t smem_u32(const void* p) {
    uint32_t a;
    asm("{ .reg .u64 t; cvta.to.shared.u64 t, %1; cvt.u32.u64 %0, t; }" : "=r"(a) : "l"(p));
    return a;
}
#define CLUSTER_ARRIVE() asm volatile("barrier.cluster.arrive.aligned;" ::: "memory")
#define CLUSTER_WAIT()   asm volatile("barrier.cluster.wait.aligned;" ::: "memory")

__device__ __forceinline__ void mmaf16(float* d, const uint32_t* a, uint32_t b0, uint32_t b1) {
    asm volatile(
        "mma.sync.aligned.m16n8k16.row.col.f32.f16.f16.f32 "
        "{%0,%1,%2,%3}, {%4,%5,%6,%7}, {%8,%9}, {%0,%1,%2,%3};"
        : "+f"(d[0]), "+f"(d[1]), "+f"(d[2]), "+f"(d[3])
        : "r"(a[0]), "r"(a[1]), "r"(a[2]), "r"(a[3]), "r"(b0), "r"(b1));
}
__device__ __forceinline__ void ldmA(uint32_t* r, uint32_t addr) {
    asm volatile("ldmatrix.sync.aligned.m8n8.x4.shared.b16 {%0,%1,%2,%3}, [%4];"
                 : "=r"(r[0]), "=r"(r[1]), "=r"(r[2]), "=r"(r[3]) : "r"(addr));
}
// full-approx activations (validated R8: rel_err 4.64e-4)
__device__ __forceinline__ float tanha(float x) {
    float y; asm("tanh.approx.f32 %0, %1;" : "=f"(y) : "f"(x)); return y;
}
__device__ __forceinline__ float sigfa(float x) {
    return fmaf(0.5f, tanha(0.5f * x), 0.5f);
}

// ======================= kernels =======================
__global__ void xT_kernel(const float* __restrict__ x) {
    int i = blockIdx.x * blockDim.x + threadIdx.x;   // i = t*1024 + b (coalesced writes)
    if (i < BATCH * SEQT) {
        int tt = i >> 10, b = i & 1023;
        g_xT[i] = x[b * SEQT + tt];
    }
}

extern "C" __global__ void __launch_bounds__(NTHREADS, 1) __cluster_dims__(CL, 1, 1)
lstm2_kernel(const float* __restrict__ Wih1, const float* __restrict__ Whh1,
             const float* __restrict__ bih1, const float* __restrict__ bhh1,
             const float* __restrict__ Wih2, const float* __restrict__ Whh2,
             const float* __restrict__ bih2, const float* __restrict__ bhh2,
             const float* __restrict__ Wl,   const float* __restrict__ bl,
             float* __restrict__ out)
{
    extern __shared__ uint32_t sm[];
    const int tid  = threadIdx.x;
    const int lane = tid & 31;
    const int wid  = tid >> 5;          // 0..7
    const int wg   = wid >> 2;          // 0 = layer-1 group, 1 = layer-2 group
    const int lwid = wid & 3;           // warp within group
    const int g    = lane >> 2;
    const int tq   = lane & 3;
    const int mhalf = lwid >> 1, qh = lwid & 1;
    const int mbase = mhalf * 32;
    const int rank = blockIdx.x & (CL - 1);
    const int b0   = (blockIdx.x / CL) * MROWS;

    float* WX  = (float*)(sm + OF_WX);
    float* BB1 = (float*)(sm + OF_BB1);
    float* BB2 = (float*)(sm + OF_BB2);

    // ---- pack weight slices into fp16 mma-fragment order ----
    // Consumption: uint4 U = ((q2*KTP + ktp)*2 + p)*32 + lane  -> word = 4*U + j
    // decode: j = idx&3, lane = (idx>>2)&31, p = (idx>>7)&1, ktp next, q2 top.
    // Fragment: gate = p*2 + (j>>1), reg = j&1;
    // B[k][n]: k0 = ktp*16 + reg*8 + 2*(lane&3), n = q2*8 + (lane>>2)
    for (int idx = tid; idx < 4096; idx += NTHREADS) {          // layer 1 (K=128)
        int j = idx & 3, ln = (idx >> 2) & 31, p = (idx >> 7) & 1;
        int ktp = (idx >> 8) & 7, q2 = idx >> 11;
        int gate = p * 2 + (j >> 1), reg = j & 1;
        int gg = ln >> 2, ttq = ln & 3;
        int k0 = ktp * 16 + reg * 8 + 2 * ttq;
        int gr = gate * HN + rank * 16 + q2 * 8 + gg;
        __half2 hv = __floats2half2_rn(Whh1[gr * HN + k0], Whh1[gr * HN + k0 + 1]);
        sm[OF_B1 + idx] = *(uint32_t*)&hv;
    }
    for (int idx = tid; idx < 8192; idx += NTHREADS) {          // layer 2 (K=256)
        int j = idx & 3, ln = (idx >> 2) & 31, p = (idx >> 7) & 1;
        int ktp = (idx >> 8) & 15, q2 = idx >> 12;
        int gate = p * 2 + (j >> 1), reg = j & 1;
        int gg = ln >> 2, ttq = ln & 3;
        int k0 = ktp * 16 + reg * 8 + 2 * ttq;
        int gr = gate * HN + rank * 16 + q2 * 8 + gg;
        float w0 = (k0 < HN)     ? Wih2[gr * HN + k0]     : Whh2[gr * HN + k0 - HN];
        float w1 = (k0 + 1 < HN) ? Wih2[gr * HN + k0 + 1] : Whh2[gr * HN + k0 + 1 - HN];
        __half2 hv = __floats2half2_rn(w0, w1);
        sm[OF_B2 + idx] = *(uint32_t*)&hv;
    }
    if (tid < 64) {
        int gt = tid >> 4, q = tid & 15;
        int gr = gt * HN + rank * 16 + q;
        WX[tid]  = Wih1[gr];
        BB1[tid] = bih1[gr] + bhh1[gr];
        BB2[tid] = bih2[gr] + bhh2[gr];
    }
    for (int i = tid; i < 64 * SAW; i += NTHREADS) sm[OF_A + i] = 0u;   // h1=h2=0
    __syncthreads();

    // per-thread rows (4) and ldmatrix addresses (per mt)
    int rows[4];
#pragma unroll
    for (int mt = 0; mt < 2; mt++)
#pragma unroll
        for (int rr = 0; rr < 2; rr++)
            rows[mt * 2 + rr] = mbase + mt * 16 + g + 8 * rr;

    const uint32_t sbA = smem_u32(sm) + OF_A * 4;
    uint32_t lmaddr[2];
#pragma unroll
    for (int mt = 0; mt < 2; mt++) {
        int row_in = mbase + mt * 16 + (lane & 7) + ((lane >> 3) & 1) * 8;
        lmaddr[mt] = sbA + (uint32_t)row_in * 528u + ((lane >> 4) & 1) * 16u;
    }
    const uint4* Bq1 = (const uint4*)(sm + OF_B1);
    const uint4* Bq2 = (const uint4*)(sm + OF_B2);

    // WG0 threads carry c1, WG1 threads carry c2 (8 cells each: 4 rows x 2 dims)
    float cc[8];
#pragma unroll
    for (int i = 0; i < 8; i++) cc[i] = 0.f;

    // gather indexing: 4 threads per row, 8 uint4 each
    const int gr_row = tid >> 2, gr_q = tid & 3;

    for (int n = 0; n <= SEQT; n++) {
        uint32_t* ghw = g_h[n & 1];

        if (wg == 0) {
            // ===== layer 1: gates1(t=n) = h1(n-1) @ Whh1^T =====
            if (n < SEQT) {
                float xtv[4];
#pragma unroll
                for (int e = 0; e < 4; e++) xtv[e] = __ldcg(&g_xT[n * BATCH + b0 + rows[e]]);

                float acc[4][2][4];
#pragma unroll
                for (int a1 = 0; a1 < 4; a1++)
#pragma unroll
                    for (int a2 = 0; a2 < 2; a2++)
#pragma unroll
                        for (int a3 = 0; a3 < 4; a3++) acc[a1][a2][a3] = 0.f;

#pragma unroll 2
                for (int ktp = 0; ktp < 8; ktp++) {
                    uint4 ba = Bq1[((qh * 8 + ktp) * 2 + 0) * 32 + lane];
                    uint4 bb = Bq1[((qh * 8 + ktp) * 2 + 1) * 32 + lane];
#pragma unroll
                    for (int mt = 0; mt < 2; mt++) {
                        uint32_t af[4];
                        ldmA(af, lmaddr[mt] + ktp * 32u);
                        mmaf16(acc[0][mt], af, ba.x, ba.y);
                        mmaf16(acc[1][mt], af, ba.z, ba.w);
                        mmaf16(acc[2][mt], af, bb.x, bb.y);
                        mmaf16(acc[3][mt], af, bb.z, bb.w);
                    }
                }
#pragma unroll
                for (int mt = 0; mt < 2; mt++)
#pragma unroll
                    for (int rr = 0; rr < 2; rr++) {
                        int e = mt * 2 + rr;
                        float hv[2];
#pragma unroll
                        for (int qq = 0; qq < 2; qq++) {
                            int fr = rr * 2 + qq;
                            int qloc = qh * 8 + tq * 2 + qq;
                            float gi = acc[0][mt][fr] + xtv[e] * WX[qloc]      + BB1[qloc];
                            float gf = acc[1][mt][fr] + xtv[e] * WX[16 + qloc] + BB1[16 + qloc];
                            float gg = acc[2][mt][fr] + xtv[e] * WX[32 + qloc] + BB1[32 + qloc];
                            float go = acc[3][mt][fr] + xtv[e] * WX[48 + qloc] + BB1[48 + qloc];
                            float iv = sigfa(gi), fv = sigfa(gf), gv = tanha(gg), ov = sigfa(go);
                            int ci = e * 2 + qq;
                            cc[ci] = fv * cc[ci] + iv * gv;
                            hv[qq] = ov * tanha(cc[ci]);
                        }
                        __half2 hp = __floats2half2_rn(hv[0], hv[1]);
                        ghw[(size_t)(b0 + rows[e]) * 128 + rank * 8 + qh * 4 + tq] = *(uint32_t*)&hp;
                    }
            }
        } else {
            // ===== layer 2: gates2(t=n-1) = [h1(n-1)|h2(n-2)] @ [Wih2|Whh2]^T =====
            if (n > 0) {
                float acc[4][2][4];
#pragma unroll
                for (int a1 = 0; a1 < 4; a1++)
#pragma unroll
                    for (int a2 = 0; a2 < 2; a2++)
#pragma unroll
                        for (int a3 = 0; a3 < 4; a3++) acc[a1][a2][a3] = 0.f;

#pragma unroll 2
                for (int ktp = 0; ktp < 16; ktp++) {
                    uint4 ba = Bq2[((qh * 16 + ktp) * 2 + 0) * 32 + lane];
                    uint4 bb = Bq2[((qh * 16 + ktp) * 2 + 1) * 32 + lane];
#pragma unroll
                    for (int mt = 0; mt < 2; mt++) {
                        uint32_t af[4];
                        ldmA(af, lmaddr[mt] + ktp * 32u);
                        mmaf16(acc[0][mt], af, ba.x, ba.y);
                        mmaf16(acc[1][mt], af, ba.z, ba.w);
                        mmaf16(acc[2][mt], af, bb.x, bb.y);
                        mmaf16(acc[3][mt], af, bb.z, bb.w);
                    }
                }
#pragma unroll
                for (int mt = 0; mt < 2; mt++)
#pragma unroll
                    for (int rr = 0; rr < 2; rr++) {
                        int e = mt * 2 + rr;
                        float hv[2];
#pragma unroll
                        for (int qq = 0; qq < 2; qq++) {
                            int fr = rr * 2 + qq;
                            int qloc = qh * 8 + tq * 2 + qq;
                            float gi = acc[0][mt][fr] + BB2[qloc];
                            float gf = acc[1][mt][fr] + BB2[16 + qloc];
                            float gg = acc[2][mt][fr] + BB2[32 + qloc];
                            float go = acc[3][mt][fr] + BB2[48 + qloc];
                            float iv = sigfa(gi), fv = sigfa(gf), gv = tanha(gg), ov = sigfa(go);
                            int ci = e * 2 + qq;
                            cc[ci] = fv * cc[ci] + iv * gv;
                            hv[qq] = ov * tanha(cc[ci]);
                        }
                        __half2 hp = __floats2half2_rn(hv[0], hv[1]);
                        ghw[(size_t)(b0 + rows[e]) * 128 + 64 + rank * 8 + qh * 4 + tq] = *(uint32_t*)&hp;
                    }
            } else {
                // h2(-1) = 0
#pragma unroll
                for (int e = 0; e < 4; e++)
                    ghw[(size_t)(b0 + rows[e]) * 128 + 64 + rank * 8 + qh * 4 + tq] = 0u;
            }
        }

        if (n < SEQT) {
            // exchange: cluster release/acquire orders STGs vs peers' __ldcg gathers
            CLUSTER_ARRIVE();
            CLUSTER_WAIT();
            // gather [h1(n) | h2(n-1)] into A tile: 4 threads per row, 8 uint4 each
            {
                const uint4* src = (const uint4*)(ghw + (size_t)(b0 + gr_row) * 128) + gr_q * 8;
                uint4* dst = (uint4*)(sm + OF_A + gr_row * SAW) + gr_q * 8;
#pragma unroll
                for (int j = 0; j < 8; j++) dst[j] = __ldcg(src + j);
            }
            __syncthreads();
        }
    }

    // ---- final linear: out[b] = h2[b,:] . Wl + bl ----
    CLUSTER_ARRIVE();
    CLUSTER_WAIT();
    if (rank == 0 && tid < MROWS) {
        const uint32_t* hr = g_h[SEQT & 1] + (size_t)(b0 + tid) * 128 + 64;
        float acc = bl[0];
#pragma unroll 16
        for (int w = 0; w < 64; w++) {
            uint32_t u = __ldcg(&hr[w]);
            float2 f = __half22float2(*(__half2*)&u);
            acc += f.x * Wl[2 * w] + f.y * Wl[2 * w + 1];
        }
        out[b0 + tid] = acc;
    }
}

// ======================= launch =======================
extern "C" void kernel_launch(void* const* d_in, const int* in_sizes, int n_in,
                              void* d_out, int out_size) {
    const float* x    = (const float*)d_in[0];
    const float* Wih1 = (const float*)d_in[1];
    const float* Whh1 = (const float*)d_in[2];
    const float* bih1 = (const float*)d_in[3];
    const float* bhh1 = (const float*)d_in[4];
    const float* Wih2 = (const float*)d_in[5];
    const float* Whh2 = (const float*)d_in[6];
    const float* bih2 = (const float*)d_in[7];
    const float* bhh2 = (const float*)d_in[8];
    const float* Wl   = (const float*)d_in[9];
    const float* bl   = (const float*)d_in[10];
    float* out = (float*)d_out;

    cudaFuncSetAttribute(lstm2_kernel, cudaFuncAttributeMaxDynamicSharedMemorySize, SMEM_BYTES);

    xT_kernel<<<(BATCH * SEQT + 255) / 256, 256>>>(x);
    lstm2_kernel<<<(BATCH / MROWS) * CL, NTHREADS, SMEM_BYTES>>>(
        Wih1, Whh1, bih1, bhh1, Wih2, Whh2, bih2, bhh2, Wl, bl, out);
}

// round 10
// speedup vs baseline: 2.2919x; 2.0316x over previous
#include <cuda_runtime.h>
#include <cuda_fp16.h>
#include <cstdint>

#define HN       128
#define BATCH    1024
#define SEQT     512
#define CL       4            // CTAs per cluster
#define MROWS    32           // batch rows per cluster
#define NTHREADS 256

#define SAW      132          // A-tile row stride in 32-bit words (264 fp16 = 528 B)

// ---- shared memory layout (32-bit word offsets) ----
#define OF_A     0                       // A tile [32][132] = 4224 words
#define OF_B1    4224                    // layer-1 B frags: 8192 words (32 KB)
#define OF_B2    (OF_B1 + 8192)          // layer-2 B frags: 16384 words (64 KB)
#define OF_WX    (OF_B2 + 16384)         // Wih1 slice   [128] floats
#define OF_BB1   (OF_WX + 128)           // bih1+bhh1    [128] floats
#define OF_BB2   (OF_BB1 + 128)          // bih2+bhh2    [128] floats
#define SMEM_WORDS (OF_BB2 + 128)
#define SMEM_BYTES (SMEM_WORDS * 4)      // ~116.9 KB

// ---- device scratch (allocation-free) ----
__device__ float    g_xT[SEQT * BATCH];      // x transposed to [T, B]
__device__ uint32_t g_h[2][BATCH * 128];     // double-buffered: per row 128 words = [h1 | h2] fp16

// ======================= helpers =======================
__device__ __forceinline__ uint32_t smem_u32(const void* p) {
    uint32_t a;
    asm("{ .reg .u64 t; cvta.to.shared.u64 t, %1; cvt.u32.u64 %0, t; }" : "=r"(a) : "l"(p));
    return a;
}
#define CLUSTER_ARRIVE() asm volatile("barrier.cluster.arrive.aligned;" ::: "memory")
#define CLUSTER_WAIT()   asm volatile("barrier.cluster.wait.aligned;" ::: "memory")

__device__ __forceinline__ void mmaf16(float* d, const uint32_t* a, uint32_t b0, uint32_t b1) {
    asm volatile(
        "mma.sync.aligned.m16n8k16.row.col.f32.f16.f16.f32 "
        "{%0,%1,%2,%3}, {%4,%5,%6,%7}, {%8,%9}, {%0,%1,%2,%3};"
        : "+f"(d[0]), "+f"(d[1]), "+f"(d[2]), "+f"(d[3])
        : "r"(a[0]), "r"(a[1]), "r"(a[2]), "r"(a[3]), "r"(b0), "r"(b1));
}
__device__ __forceinline__ void ldmA(uint32_t* r, uint32_t addr) {
    asm volatile("ldmatrix.sync.aligned.m8n8.x4.shared.b16 {%0,%1,%2,%3}, [%4];"
                 : "=r"(r[0]), "=r"(r[1]), "=r"(r[2]), "=r"(r[3]) : "r"(addr));
}
// full-approx activations (validated: rel_err 4.64e-4)
__device__ __forceinline__ float tanha(float x) {
    float y; asm("tanh.approx.f32 %0, %1;" : "=f"(y) : "f"(x)); return y;
}
__device__ __forceinline__ float sigfa(float x) {
    return fmaf(0.5f, tanha(0.5f * x), 0.5f);
}

// ======================= kernels =======================
__global__ void xT_kernel(const float* __restrict__ x) {
    int i = blockIdx.x * blockDim.x + threadIdx.x;   // i = t*1024 + b (coalesced writes)
    if (i < BATCH * SEQT) {
        int tt = i >> 10, b = i & 1023;
        g_xT[i] = x[b * SEQT + tt];
    }
}

extern "C" __global__ void __launch_bounds__(NTHREADS, 1) __cluster_dims__(CL, 1, 1)
lstm2_kernel(const float* __restrict__ Wih1, const float* __restrict__ Whh1,
             const float* __restrict__ bih1, const float* __restrict__ bhh1,
             const float* __restrict__ Wih2, const float* __restrict__ Whh2,
             const float* __restrict__ bih2, const float* __restrict__ bhh2,
             const float* __restrict__ Wl,   const float* __restrict__ bl,
             float* __restrict__ out)
{
    extern __shared__ uint32_t sm[];
    const int tid  = threadIdx.x;
    const int lane = tid & 31;
    const int wid  = tid >> 5;          // 0..7
    const int wg   = wid >> 2;          // 0 = layer-1 group, 1 = layer-2 group
    const int lwid = wid & 3;           // warp within group
    const int g    = lane >> 2;
    const int tq   = lane & 3;
    const int mhalf = lwid >> 1;        // M16 tile (M=32 -> 2 tiles)
    const int qh    = lwid & 1;         // 16-dim half of the CTA's 32-dim slice
    const int mbase = mhalf * 16;
    const int rank = blockIdx.x & (CL - 1);
    const int b0   = (blockIdx.x / CL) * MROWS;

    float* WX  = (float*)(sm + OF_WX);
    float* BB1 = (float*)(sm + OF_BB1);
    float* BB2 = (float*)(sm + OF_BB2);

    // ---- pack weight slices into fp16 mma-fragment order ----
    // Consumption: uint4 U = ((qh*KTP + ktp)*4 + s)*32 + lane, word = 4*U + j
    // s = qs*2 + p (qs = q8 within half, p = gate pair); gate = p*2 + (j>>1), reg = j&1
    // B[k][n]: k0 = ktp*16 + reg*8 + 2*(lane&3); dim = (2*qh+qs)*8 + (lane>>2)
    for (int idx = tid; idx < 8192; idx += NTHREADS) {          // layer 1 (K=128, KTP=8)
        int j = idx & 3, ln = (idx >> 2) & 31, s = (idx >> 7) & 3;
        int ktp = (idx >> 9) & 7, qhh = idx >> 12;
        int qs = s >> 1, p = s & 1;
        int gate = p * 2 + (j >> 1), reg = j & 1;
        int k0 = ktp * 16 + reg * 8 + 2 * (ln & 3);
        int qd = (2 * qhh + qs) * 8 + (ln >> 2);
        int gr = gate * HN + rank * 32 + qd;
        __half2 hv = __floats2half2_rn(Whh1[gr * HN + k0], Whh1[gr * HN + k0 + 1]);
        sm[OF_B1 + idx] = *(uint32_t*)&hv;
    }
    for (int idx = tid; idx < 16384; idx += NTHREADS) {         // layer 2 (K=256, KTP=16)
        int j = idx & 3, ln = (idx >> 2) & 31, s = (idx >> 7) & 3;
        int ktp = (idx >> 9) & 15, qhh = idx >> 13;
        int qs = s >> 1, p = s & 1;
        int gate = p * 2 + (j >> 1), reg = j & 1;
        int k0 = ktp * 16 + reg * 8 + 2 * (ln & 3);
        int qd = (2 * qhh + qs) * 8 + (ln >> 2);
        int gr = gate * HN + rank * 32 + qd;
        float w0 = (k0 < HN)     ? Wih2[gr * HN + k0]     : Whh2[gr * HN + k0 - HN];
        float w1 = (k0 + 1 < HN) ? Wih2[gr * HN + k0 + 1] : Whh2[gr * HN + k0 + 1 - HN];
        __half2 hv = __floats2half2_rn(w0, w1);
        sm[OF_B2 + idx] = *(uint32_t*)&hv;
    }
    if (tid < 128) {
        int gt = tid >> 5, q = tid & 31;
        int gr = gt * HN + rank * 32 + q;
        WX[tid]  = Wih1[gr];
        BB1[tid] = bih1[gr] + bhh1[gr];
        BB2[tid] = bih2[gr] + bhh2[gr];
    }
    for (int i = tid; i < MROWS * SAW; i += NTHREADS) sm[OF_A + i] = 0u;   // h1=h2=0
    __syncthreads();

    // per-thread rows (2) and ldmatrix address
    int rows[2];
    rows[0] = mbase + g;
    rows[1] = mbase + g + 8;

    const uint32_t sbA = smem_u32(sm) + OF_A * 4;
    const int row_in = mbase + (lane & 7) + ((lane >> 3) & 1) * 8;
    const uint32_t lmaddr = sbA + (uint32_t)row_in * 528u + ((lane >> 4) & 1) * 16u;

    const uint4* Bq1 = (const uint4*)(sm + OF_B1);
    const uint4* Bq2 = (const uint4*)(sm + OF_B2);

    // WG0 carries c1, WG1 carries c2: 8 cells (2 rows x 2 qs x 2 qq)
    float cc[8];
#pragma unroll
    for (int i = 0; i < 8; i++) cc[i] = 0.f;

    // gather indexing: 8 threads per row, 4 uint4 each (128 words/row)
    const int gr_row = tid >> 3, gr_part = tid & 7;

    for (int n = 0; n <= SEQT; n++) {
        uint32_t* ghw = g_h[n & 1];

        if (wg == 0) {
            // ===== layer 1: gates1(t=n) = h1(n-1) @ Whh1^T =====
            if (n < SEQT) {
                float xtv[2];
#pragma unroll
                for (int e = 0; e < 2; e++) xtv[e] = __ldcg(&g_xT[n * BATCH + b0 + rows[e]]);

                float acc[4][2][4];
#pragma unroll
                for (int a1 = 0; a1 < 4; a1++)
#pragma unroll
                    for (int a2 = 0; a2 < 2; a2++)
#pragma unroll
                        for (int a3 = 0; a3 < 4; a3++) acc[a1][a2][a3] = 0.f;

#pragma unroll 2
                for (int ktp = 0; ktp < 8; ktp++) {
                    int base = (qh * 8 + ktp) * 4;
                    uint4 b0v = Bq1[(base + 0) * 32 + lane];
                    uint4 b1v = Bq1[(base + 1) * 32 + lane];
                    uint4 b2v = Bq1[(base + 2) * 32 + lane];
                    uint4 b3v = Bq1[(base + 3) * 32 + lane];
                    uint32_t af[4];
                    ldmA(af, lmaddr + ktp * 32u);
                    mmaf16(acc[0][0], af, b0v.x, b0v.y);
                    mmaf16(acc[1][0], af, b0v.z, b0v.w);
                    mmaf16(acc[2][0], af, b1v.x, b1v.y);
                    mmaf16(acc[3][0], af, b1v.z, b1v.w);
                    mmaf16(acc[0][1], af, b2v.x, b2v.y);
                    mmaf16(acc[1][1], af, b2v.z, b2v.w);
                    mmaf16(acc[2][1], af, b3v.x, b3v.y);
                    mmaf16(acc[3][1], af, b3v.z, b3v.w);
                }
#pragma unroll
                for (int e = 0; e < 2; e++)
#pragma unroll
                    for (int qs = 0; qs < 2; qs++) {
                        float hv[2];
#pragma unroll
                        for (int qq = 0; qq < 2; qq++) {
                            int fr = e * 2 + qq;
                            int qloc = (2 * qh + qs) * 8 + tq * 2 + qq;
                            float gi = acc[0][qs][fr] + xtv[e] * WX[qloc]      + BB1[qloc];
                            float gf = acc[1][qs][fr] + xtv[e] * WX[32 + qloc] + BB1[32 + qloc];
                            float gg = acc[2][qs][fr] + xtv[e] * WX[64 + qloc] + BB1[64 + qloc];
                            float go = acc[3][qs][fr] + xtv[e] * WX[96 + qloc] + BB1[96 + qloc];
                            float iv = sigfa(gi), fv = sigfa(gf), gv = tanha(gg), ov = sigfa(go);
                            int ci = e * 4 + qs * 2 + qq;
                            cc[ci] = fv * cc[ci] + iv * gv;
                            hv[qq] = ov * tanha(cc[ci]);
                        }
                        __half2 hp = __floats2half2_rn(hv[0], hv[1]);
                        ghw[(size_t)(b0 + rows[e]) * 128 + rank * 16 + (2 * qh + qs) * 4 + tq]
                            = *(uint32_t*)&hp;
                    }
            }
        } else {
            // ===== layer 2: gates2(t=n-1) = [h1(n-1)|h2(n-2)] @ [Wih2|Whh2]^T =====
            if (n > 0) {
                float acc[4][2][4];
#pragma unroll
                for (int a1 = 0; a1 < 4; a1++)
#pragma unroll
                    for (int a2 = 0; a2 < 2; a2++)
#pragma unroll
                        for (int a3 = 0; a3 < 4; a3++) acc[a1][a2][a3] = 0.f;

#pragma unroll 2
                for (int ktp = 0; ktp < 16; ktp++) {
                    int base = (qh * 16 + ktp) * 4;
                    uint4 b0v = Bq2[(base + 0) * 32 + lane];
                    uint4 b1v = Bq2[(base + 1) * 32 + lane];
                    uint4 b2v = Bq2[(base + 2) * 32 + lane];
                    uint4 b3v = Bq2[(base + 3) * 32 + lane];
                    uint32_t af[4];
                    ldmA(af, lmaddr + ktp * 32u);
                    mmaf16(acc[0][0], af, b0v.x, b0v.y);
                    mmaf16(acc[1][0], af, b0v.z, b0v.w);
                    mmaf16(acc[2][0], af, b1v.x, b1v.y);
                    mmaf16(acc[3][0], af, b1v.z, b1v.w);
                    mmaf16(acc[0][1], af, b2v.x, b2v.y);
                    mmaf16(acc[1][1], af, b2v.z, b2v.w);
                    mmaf16(acc[2][1], af, b3v.x, b3v.y);
                    mmaf16(acc[3][1], af, b3v.z, b3v.w);
                }
#pragma unroll
                for (int e = 0; e < 2; e++)
#pragma unroll
                    for (int qs = 0; qs < 2; qs++) {
                        float hv[2];
#pragma unroll
                        for (int qq = 0; qq < 2; qq++) {
                            int fr = e * 2 + qq;
                            int qloc = (2 * qh + qs) * 8 + tq * 2 + qq;
                            float gi = acc[0][qs][fr] + BB2[qloc];
                            float gf = acc[1][qs][fr] + BB2[32 + qloc];
                            float gg = acc[2][qs][fr] + BB2[64 + qloc];
                            float go = acc[3][qs][fr] + BB2[96 + qloc];
                            float iv = sigfa(gi), fv = sigfa(gf), gv = tanha(gg), ov = sigfa(go);
                            int ci = e * 4 + qs * 2 + qq;
                            cc[ci] = fv * cc[ci] + iv * gv;
                            hv[qq] = ov * tanha(cc[ci]);
                        }
                        __half2 hp = __floats2half2_rn(hv[0], hv[1]);
                        ghw[(size_t)(b0 + rows[e]) * 128 + 64 + rank * 16 + (2 * qh + qs) * 4 + tq]
                            = *(uint32_t*)&hp;
                    }
            } else {
                // h2(-1) = 0
#pragma unroll
                for (int e = 0; e < 2; e++)
#pragma unroll
                    for (int qs = 0; qs < 2; qs++)
                        ghw[(size_t)(b0 + rows[e]) * 128 + 64 + rank * 16 + (2 * qh + qs) * 4 + tq] = 0u;
            }
        }

        if (n < SEQT) {
            // exchange: cluster release/acquire orders STGs vs peers' __ldcg gathers
            CLUSTER_ARRIVE();
            CLUSTER_WAIT();
            // gather [h1(n) | h2(n-1)] into A tile: 8 threads/row, 4 uint4 each
            {
                const uint4* src = (const uint4*)(ghw + (size_t)(b0 + gr_row) * 128) + gr_part * 4;
                uint4* dst = (uint4*)(sm + OF_A + gr_row * SAW) + gr_part * 4;
#pragma unroll
                for (int j = 0; j < 4; j++) dst[j] = __ldcg(src + j);
            }
            __syncthreads();
        }
    }

    // ---- final linear: out[b] = h2[b,:] . Wl + bl ----
    CLUSTER_ARRIVE();
    CLUSTER_WAIT();
    if (rank == 0 && tid < MROWS) {
        const uint32_t* hr = g_h[SEQT & 1] + (size_t)(b0 + tid) * 128 + 64;
        float acc = bl[0];
#pragma unroll 16
        for (int w = 0; w < 64; w++) {
            uint32_t u = __ldcg(&hr[w]);
            float2 f = __half22float2(*(__half2*)&u);
            acc += f.x * Wl[2 * w] + f.y * Wl[2 * w + 1];
        }
        out[b0 + tid] = acc;
    }
}

// ======================= launch =======================
extern "C" void kernel_launch(void* const* d_in, const int* in_sizes, int n_in,
                              void* d_out, int out_size) {
    const float* x    = (const float*)d_in[0];
    const float* Wih1 = (const float*)d_in[1];
    const float* Whh1 = (const float*)d_in[2];
    const float* bih1 = (const float*)d_in[3];
    const float* bhh1 = (const float*)d_in[4];
    const float* Wih2 = (const float*)d_in[5];
    const float* Whh2 = (const float*)d_in[6];
    const float* bih2 = (const float*)d_in[7];
    const float* bhh2 = (const float*)d_in[8];
    const float* Wl   = (const float*)d_in[9];
    const float* bl   = (const float*)d_in[10];
    float* out = (float*)d_out;

    cudaFuncSetAttribute(lstm2_kernel, cudaFuncAttributeMaxDynamicSharedMemorySize, SMEM_BYTES);

    xT_kernel<<<(BATCH * SEQT + 255) / 256, 256>>>(x);
    lstm2_kernel<<<(BATCH / MROWS) * CL, NTHREADS, SMEM_BYTES>>>(
        Wih1, Whh1, bih1, bhh1, Wih2, Whh2, bih2, bhh2, Wl, bl, out);
}

// round 11
// speedup vs baseline: 2.5113x; 1.0957x over previous
#include <cuda_runtime.h>
#include <cuda_fp16.h>
#include <cstdint>

#define HN       128
#define BATCH    1024
#define SEQT     512
#define CL       2            // CTAs per cluster
#define MROWS    16           // batch rows per cluster
#define NTHREADS 256

#define SAW      132          // A-tile row stride in 32-bit words (264 fp16 = 528 B)

// ---- shared memory layout (32-bit word offsets) ----
#define OF_A     0                       // A tile [16][132] = 2112 words
#define OF_B1    2112                    // layer-1 B frags: 16384 words (64 KB)
#define OF_B2    (OF_B1 + 16384)         // layer-2 B frags: 32768 words (128 KB)
#define OF_WX    (OF_B2 + 32768)         // Wih1 slice   [256] floats (4 gates x 64 dims)
#define OF_BB1   (OF_WX + 256)           // bih1+bhh1    [256] floats
#define OF_BB2   (OF_BB1 + 256)          // bih2+bhh2    [256] floats
#define SMEM_WORDS (OF_BB2 + 256)
#define SMEM_BYTES (SMEM_WORDS * 4)      // 208,128 B (~203 KB)

// ---- device scratch (allocation-free) ----
__device__ float    g_xT[SEQT * BATCH];      // x transposed to [T, B]
__device__ uint32_t g_h[2][BATCH * 128];     // double-buffered: per row 128 words = [h1 | h2] fp16

// ======================= helpers =======================
__device__ __forceinline__ uint32_t smem_u32(const void* p) {
    uint32_t a;
    asm("{ .reg .u64 t; cvta.to.shared.u64 t, %1; cvt.u32.u64 %0, t; }" : "=r"(a) : "l"(p));
    return a;
}
#define CLUSTER_ARRIVE() asm volatile("barrier.cluster.arrive.aligned;" ::: "memory")
#define CLUSTER_WAIT()   asm volatile("barrier.cluster.wait.aligned;" ::: "memory")

__device__ __forceinline__ void mmaf16(float* d, const uint32_t* a, uint32_t b0, uint32_t b1) {
    asm volatile(
        "mma.sync.aligned.m16n8k16.row.col.f32.f16.f16.f32 "
        "{%0,%1,%2,%3}, {%4,%5,%6,%7}, {%8,%9}, {%0,%1,%2,%3};"
        : "+f"(d[0]), "+f"(d[1]), "+f"(d[2]), "+f"(d[3])
        : "r"(a[0]), "r"(a[1]), "r"(a[2]), "r"(a[3]), "r"(b0), "r"(b1));
}
__device__ __forceinline__ void ldmA(uint32_t* r, uint32_t addr) {
    asm volatile("ldmatrix.sync.aligned.m8n8.x4.shared.b16 {%0,%1,%2,%3}, [%4];"
                 : "=r"(r[0]), "=r"(r[1]), "=r"(r[2]), "=r"(r[3]) : "r"(addr));
}
// full-approx activations (validated: rel_err 4.64e-4)
__device__ __forceinline__ float tanha(float x) {
    float y; asm("tanh.approx.f32 %0, %1;" : "=f"(y) : "f"(x)); return y;
}
__device__ __forceinline__ float sigfa(float x) {
    return fmaf(0.5f, tanha(0.5f * x), 0.5f);
}

// ======================= kernels =======================
__global__ void xT_kernel(const float* __restrict__ x) {
    int i = blockIdx.x * blockDim.x + threadIdx.x;   // i = t*1024 + b (coalesced writes)
    if (i < BATCH * SEQT) {
        int tt = i >> 10, b = i & 1023;
        g_xT[i] = x[b * SEQT + tt];
    }
}

extern "C" __global__ void __launch_bounds__(NTHREADS, 1) __cluster_dims__(CL, 1, 1)
lstm2_kernel(const float* __restrict__ Wih1, const float* __restrict__ Whh1,
             const float* __restrict__ bih1, const float* __restrict__ bhh1,
             const float* __restrict__ Wih2, const float* __restrict__ Whh2,
             const float* __restrict__ bih2, const float* __restrict__ bhh2,
             const float* __restrict__ Wl,   const float* __restrict__ bl,
             float* __restrict__ out)
{
    extern __shared__ uint32_t sm[];
    const int tid  = threadIdx.x;
    const int lane = tid & 31;
    const int wid  = tid >> 5;          // 0..7
    const int wg   = wid >> 2;          // 0 = layer-1 group, 1 = layer-2 group
    const int lwid = wid & 3;           // warp within group -> 16-dim slice
    const int g    = lane >> 2;
    const int tq   = lane & 3;
    const int rank = blockIdx.x & (CL - 1);
    const int b0   = (blockIdx.x / CL) * MROWS;

    float* WX  = (float*)(sm + OF_WX);
    float* BB1 = (float*)(sm + OF_BB1);
    float* BB2 = (float*)(sm + OF_BB2);

    // ---- pack weight slices into fp16 mma-fragment order ----
    // Consumption (warp w = lwid): uint4 U = (((w*2 + q2)*KTP + ktp)*2 + p)*32 + lane,
    // word = 4*U + j; gate = p*2 + (j>>1), reg = j&1;
    // B[k][dim]: k0 = ktp*16 + reg*8 + 2*(lane&3); dim = w*16 + q2*8 + (lane>>2)
    for (int idx = tid; idx < 16384; idx += NTHREADS) {         // layer 1 (K=128, KTP=8)
        int j = idx & 3, ln = (idx >> 2) & 31, p = (idx >> 7) & 1;
        int ktp = (idx >> 8) & 7, q2 = (idx >> 11) & 1, w = idx >> 12;
        int gate = p * 2 + (j >> 1), reg = j & 1;
        int k0 = ktp * 16 + reg * 8 + 2 * (ln & 3);
        int dim = w * 16 + q2 * 8 + (ln >> 2);
        int gr = gate * HN + rank * 64 + dim;
        __half2 hv = __floats2half2_rn(Whh1[gr * HN + k0], Whh1[gr * HN + k0 + 1]);
        sm[OF_B1 + idx] = *(uint32_t*)&hv;
    }
    for (int idx = tid; idx < 32768; idx += NTHREADS) {         // layer 2 (K=256, KTP=16)
        int j = idx & 3, ln = (idx >> 2) & 31, p = (idx >> 7) & 1;
        int ktp = (idx >> 8) & 15, q2 = (idx >> 12) & 1, w = idx >> 13;
        int gate = p * 2 + (j >> 1), reg = j & 1;
        int k0 = ktp * 16 + reg * 8 + 2 * (ln & 3);
        int dim = w * 16 + q2 * 8 + (ln >> 2);
        int gr = gate * HN + rank * 64 + dim;
        float w0 = (k0 < HN)     ? Wih2[gr * HN + k0]     : Whh2[gr * HN + k0 - HN];
        float w1 = (k0 + 1 < HN) ? Wih2[gr * HN + k0 + 1] : Whh2[gr * HN + k0 + 1 - HN];
        __half2 hv = __floats2half2_rn(w0, w1);
        sm[OF_B2 + idx] = *(uint32_t*)&hv;
    }
    {   // WX / biases: 4 gates x 64 dims
        int gt = tid >> 6, q = tid & 63;
        int gr = gt * HN + rank * 64 + q;
        WX[tid]  = Wih1[gr];
        BB1[tid] = bih1[gr] + bhh1[gr];
        BB2[tid] = bih2[gr] + bhh2[gr];
    }
    for (int i = tid; i < MROWS * SAW; i += NTHREADS) sm[OF_A + i] = 0u;   // h1=h2=0
    __syncthreads();

    // per-thread rows (2) and ldmatrix address (single M16 tile)
    int rows[2];
    rows[0] = g;
    rows[1] = g + 8;

    const uint32_t sbA = smem_u32(sm) + OF_A * 4;
    const uint32_t lmaddr = sbA + (uint32_t)(lane & 15) * 528u + ((lane >> 4) & 1) * 16u;

    const uint4* Bq1 = (const uint4*)(sm + OF_B1);
    const uint4* Bq2 = (const uint4*)(sm + OF_B2);

    // WG0 carries c1, WG1 carries c2: 8 cells (2 rows x 2 q2 x 2 qq)
    float cc[8];
#pragma unroll
    for (int i = 0; i < 8; i++) cc[i] = 0.f;

    // gather indexing: 16 threads per row, 2 uint4 each (32 uint4 per row)
    const int gr_row = tid >> 4, gr_part = tid & 15;

    for (int n = 0; n <= SEQT; n++) {
        uint32_t* ghw = g_h[n & 1];

        if (wg == 0) {
            // ===== layer 1: gates1(t=n) = h1(n-1) @ Whh1^T =====
            if (n < SEQT) {
                float xtv[2];
#pragma unroll
                for (int e = 0; e < 2; e++) xtv[e] = __ldcg(&g_xT[n * BATCH + b0 + rows[e]]);

                float acc[4][2][4];
#pragma unroll
                for (int a1 = 0; a1 < 4; a1++)
#pragma unroll
                    for (int a2 = 0; a2 < 2; a2++)
#pragma unroll
                        for (int a3 = 0; a3 < 4; a3++) acc[a1][a2][a3] = 0.f;

#pragma unroll 2
                for (int ktp = 0; ktp < 8; ktp++) {
                    int base = (lwid * 2) * 8 + ktp;            // (w*2+q2)*KTP + ktp, q2=0
                    uint4 b0v = Bq1[((base) * 2 + 0) * 32 + lane];
                    uint4 b1v = Bq1[((base) * 2 + 1) * 32 + lane];
                    uint4 b2v = Bq1[((base + 8) * 2 + 0) * 32 + lane];   // q2=1 -> +KTP
                    uint4 b3v = Bq1[((base + 8) * 2 + 1) * 32 + lane];
                    uint32_t af[4];
                    ldmA(af, lmaddr + ktp * 32u);
                    mmaf16(acc[0][0], af, b0v.x, b0v.y);
                    mmaf16(acc[1][0], af, b0v.z, b0v.w);
                    mmaf16(acc[2][0], af, b1v.x, b1v.y);
                    mmaf16(acc[3][0], af, b1v.z, b1v.w);
                    mmaf16(acc[0][1], af, b2v.x, b2v.y);
                    mmaf16(acc[1][1], af, b2v.z, b2v.w);
                    mmaf16(acc[2][1], af, b3v.x, b3v.y);
                    mmaf16(acc[3][1], af, b3v.z, b3v.w);
                }
#pragma unroll
                for (int e = 0; e < 2; e++)
#pragma unroll
                    for (int q2 = 0; q2 < 2; q2++) {
                        float hv[2];
#pragma unroll
                        for (int qq = 0; qq < 2; qq++) {
                            int fr = e * 2 + qq;
                            int qloc = lwid * 16 + q2 * 8 + tq * 2 + qq;   // dim within 64
                            float gi = acc[0][q2][fr] + xtv[e] * WX[qloc]       + BB1[qloc];
                            float gf = acc[1][q2][fr] + xtv[e] * WX[64 + qloc]  + BB1[64 + qloc];
                            float gg = acc[2][q2][fr] + xtv[e] * WX[128 + qloc] + BB1[128 + qloc];
                            float go = acc[3][q2][fr] + xtv[e] * WX[192 + qloc] + BB1[192 + qloc];
                            float iv = sigfa(gi), fv = sigfa(gf), gv = tanha(gg), ov = sigfa(go);
                            int ci = e * 4 + q2 * 2 + qq;
                            cc[ci] = fv * cc[ci] + iv * gv;
                            hv[qq] = ov * tanha(cc[ci]);
                        }
                        __half2 hp = __floats2half2_rn(hv[0], hv[1]);
                        ghw[(size_t)(b0 + rows[e]) * 128 + rank * 32 + lwid * 8 + q2 * 4 + tq]
                            = *(uint32_t*)&hp;
                    }
            }
        } else {
            // ===== layer 2: gates2(t=n-1) = [h1(n-1)|h2(n-2)] @ [Wih2|Whh2]^T =====
            if (n > 0) {
                float acc[4][2][4];
#pragma unroll
                for (int a1 = 0; a1 < 4; a1++)
#pragma unroll
                    for (int a2 = 0; a2 < 2; a2++)
#pragma unroll
                        for (int a3 = 0; a3 < 4; a3++) acc[a1][a2][a3] = 0.f;

#pragma unroll 2
                for (int ktp = 0; ktp < 16; ktp++) {
                    int base = (lwid * 2) * 16 + ktp;
                    uint4 b0v = Bq2[((base) * 2 + 0) * 32 + lane];
                    uint4 b1v = Bq2[((base) * 2 + 1) * 32 + lane];
                    uint4 b2v = Bq2[((base + 16) * 2 + 0) * 32 + lane];
                    uint4 b3v = Bq2[((base + 16) * 2 + 1) * 32 + lane];
                    uint32_t af[4];
                    ldmA(af, lmaddr + ktp * 32u);
                    mmaf16(acc[0][0], af, b0v.x, b0v.y);
                    mmaf16(acc[1][0], af, b0v.z, b0v.w);
                    mmaf16(acc[2][0], af, b1v.x, b1v.y);
                    mmaf16(acc[3][0], af, b1v.z, b1v.w);
                    mmaf16(acc[0][1], af, b2v.x, b2v.y);
                    mmaf16(acc[1][1], af, b2v.z, b2v.w);
                    mmaf16(acc[2][1], af, b3v.x, b3v.y);
                    mmaf16(acc[3][1], af, b3v.z, b3v.w);
                }
#pragma unroll
                for (int e = 0; e < 2; e++)
#pragma unroll
                    for (int q2 = 0; q2 < 2; q2++) {
                        float hv[2];
#pragma unroll
                        for (int qq = 0; qq < 2; qq++) {
                            int fr = e * 2 + qq;
                            int qloc = lwid * 16 + q2 * 8 + tq * 2 + qq;
                            float gi = acc[0][q2][fr] + BB2[qloc];
                            float gf = acc[1][q2][fr] + BB2[64 + qloc];
                            float gg = acc[2][q2][fr] + BB2[128 + qloc];
                            float go = acc[3][q2][fr] + BB2[192 + qloc];
                            float iv = sigfa(gi), fv = sigfa(gf), gv = tanha(gg), ov = sigfa(go);
                            int ci = e * 4 + q2 * 2 + qq;
                            cc[ci] = fv * cc[ci] + iv * gv;
                            hv[qq] = ov * tanha(cc[ci]);
                        }
                        __half2 hp = __floats2half2_rn(hv[0], hv[1]);
                        ghw[(size_t)(b0 + rows[e]) * 128 + 64 + rank * 32 + lwid * 8 + q2 * 4 + tq]
                            = *(uint32_t*)&hp;
                    }
            } else {
                // h2(-1) = 0
#pragma unroll
                for (int e = 0; e < 2; e++)
#pragma unroll
                    for (int q2 = 0; q2 < 2; q2++)
                        ghw[(size_t)(b0 + rows[e]) * 128 + 64 + rank * 32 + lwid * 8 + q2 * 4 + tq] = 0u;
            }
        }

        if (n < SEQT) {
            // exchange: cluster release/acquire orders STGs vs peers' __ldcg gathers
            CLUSTER_ARRIVE();
            CLUSTER_WAIT();
            // gather [h1(n) | h2(n-1)] into A tile: 16 threads/row, 2 uint4 each
            {
                const uint4* src = (const uint4*)(ghw + (size_t)(b0 + gr_row) * 128) + gr_part * 2;
                uint4* dst = (uint4*)(sm + OF_A + gr_row * SAW) + gr_part * 2;
                dst[0] = __ldcg(src + 0);
                dst[1] = __ldcg(src + 1);
            }
            __syncthreads();
        }
    }

    // ---- final linear: out[b] = h2[b,:] . Wl + bl ----
    CLUSTER_ARRIVE();
    CLUSTER_WAIT();
    if (rank == 0 && tid < MROWS) {
        const uint32_t* hr = g_h[SEQT & 1] + (size_t)(b0 + tid) * 128 + 64;
        float acc = bl[0];
#pragma unroll 16
        for (int w = 0; w < 64; w++) {
            uint32_t u = __ldcg(&hr[w]);
            float2 f = __half22float2(*(__half2*)&u);
            acc += f.x * Wl[2 * w] + f.y * Wl[2 * w + 1];
        }
        out[b0 + tid] = acc;
    }
}

// ======================= launch =======================
extern "C" void kernel_launch(void* const* d_in, const int* in_sizes, int n_in,
                              void* d_out, int out_size) {
    const float* x    = (const float*)d_in[0];
    const float* Wih1 = (const float*)d_in[1];
    const float* Whh1 = (const float*)d_in[2];
    const float* bih1 = (const float*)d_in[3];
    const float* bhh1 = (const float*)d_in[4];
    const float* Wih2 = (const float*)d_in[5];
    const float* Whh2 = (const float*)d_in[6];
    const float* bih2 = (const float*)d_in[7];
    const float* bhh2 = (const float*)d_in[8];
    const float* Wl   = (const float*)d_in[9];
    const float* bl   = (const float*)d_in[10];
    float* out = (float*)d_out;

    cudaFuncSetAttribute(lstm2_kernel, cudaFuncAttributeMaxDynamicSharedMemorySize, SMEM_BYTES);

    xT_kernel<<<(BATCH * SEQT + 255) / 256, 256>>>(x);
    lstm2_kernel<<<(BATCH / MROWS) * CL, NTHREADS, SMEM_BYTES>>>(
        Wih1, Whh1, bih1, bhh1, Wih2, Whh2, bih2, bhh2, Wl, bl, out);
}

// round 13
// speedup vs baseline: 3.5428x; 1.4108x over previous
#include <cuda_runtime.h>
#include <cuda_fp16.h>
#include <cstdint>

#define HN       128
#define BATCH    1024
#define SEQT     512
#define CL       2            // CTAs per cluster
#define MROWS    16           // batch rows per cluster
#define NTHREADS 256

#define SAW      132          // A-tile row stride in 32-bit words (264 fp16 = 528 B)
#define AWORDS   (MROWS * SAW)           // 2112 words per A buffer
#define ABYTES   (AWORDS * 4)            // 8448 B

// ---- shared memory layout (32-bit word offsets) ----
#define OF_A     0                       // A tiles x2 (parity) = 4224 words
#define OF_B1    (2 * AWORDS)            // layer-1 B frags: 16384 words (64 KB)
#define OF_B2    (OF_B1 + 16384)         // layer-2 B frags: 32768 words (128 KB)
#define OF_WX    (OF_B2 + 32768)         // Wih1 slice   [256] floats (4 gates x 64 dims)
#define OF_BB1   (OF_WX + 256)           // bih1+bhh1    [256] floats
#define OF_BB2   (OF_BB1 + 256)          // bih2+bhh2    [256] floats
#define SMEM_WORDS (OF_BB2 + 256)
#define SMEM_BYTES (SMEM_WORDS * 4)      // 216,576 B

// ---- device scratch (allocation-free) ----
__device__ float g_xT[SEQT * BATCH];     // x transposed to [T, B]

// ======================= helpers =======================
__device__ __forceinline__ uint32_t smem_u32(const void* p) {
    uint32_t a;
    asm("{ .reg .u64 t; cvta.to.shared.u64 t, %1; cvt.u32.u64 %0, t; }" : "=r"(a) : "l"(p));
    return a;
}
__device__ __forceinline__ uint32_t mapa_u32(uint32_t addr, int r) {
    uint32_t o;
    asm("mapa.shared::cluster.u32 %0, %1, %2;" : "=r"(o) : "r"(addr), "r"(r));
    return o;
}
#define CLUSTER_ARRIVE() asm volatile("barrier.cluster.arrive.aligned;" ::: "memory")
#define CLUSTER_WAIT()   asm volatile("barrier.cluster.wait.aligned;" ::: "memory")
#define STSC(addr, v)    asm volatile("st.shared::cluster.u32 [%0], %1;" :: "r"(addr), "r"(v) : "memory")

__device__ __forceinline__ void mmaf16(float* d, const uint32_t* a, uint32_t b0, uint32_t b1) {
    asm volatile(
        "mma.sync.aligned.m16n8k16.row.col.f32.f16.f16.f32 "
        "{%0,%1,%2,%3}, {%4,%5,%6,%7}, {%8,%9}, {%0,%1,%2,%3};"
        : "+f"(d[0]), "+f"(d[1]), "+f"(d[2]), "+f"(d[3])
        : "r"(a[0]), "r"(a[1]), "r"(a[2]), "r"(a[3]), "r"(b0), "r"(b1));
}
__device__ __forceinline__ void ldmA(uint32_t* r, uint32_t addr) {
    asm volatile("ldmatrix.sync.aligned.m8n8.x4.shared.b16 {%0,%1,%2,%3}, [%4];"
                 : "=r"(r[0]), "=r"(r[1]), "=r"(r[2]), "=r"(r[3]) : "r"(addr));
}
// full-approx activations (validated: rel_err 4.64e-4)
__device__ __forceinline__ float tanha(float x) {
    float y; asm("tanh.approx.f32 %0, %1;" : "=f"(y) : "f"(x)); return y;
}
__device__ __forceinline__ float sigfa(float x) {
    return fmaf(0.5f, tanha(0.5f * x), 0.5f);
}

// ======================= kernels =======================
__global__ void xT_kernel(const float* __restrict__ x) {
    int i = blockIdx.x * blockDim.x + threadIdx.x;   // i = t*1024 + b (coalesced writes)
    if (i < BATCH * SEQT) {
        int tt = i >> 10, b = i & 1023;
        g_xT[i] = x[b * SEQT + tt];
    }
}

extern "C" __global__ void __launch_bounds__(NTHREADS, 1) __cluster_dims__(CL, 1, 1)
lstm2_kernel(const float* __restrict__ Wih1, const float* __restrict__ Whh1,
             const float* __restrict__ bih1, const float* __restrict__ bhh1,
             const float* __restrict__ Wih2, const float* __restrict__ Whh2,
             const float* __restrict__ bih2, const float* __restrict__ bhh2,
             const float* __restrict__ Wl,   const float* __restrict__ bl,
             float* __restrict__ out)
{
    extern __shared__ uint32_t sm[];
    const int tid  = threadIdx.x;
    const int lane = tid & 31;
    const int wid  = tid >> 5;          // 0..7
    const int wg   = wid >> 2;          // 0 = layer-1 group, 1 = layer-2 group
    const int lwid = wid & 3;           // warp within group -> 16-dim slice
    const int g    = lane >> 2;
    const int tq   = lane & 3;
    const int rank = blockIdx.x & (CL - 1);
    const int b0   = (blockIdx.x / CL) * MROWS;

    float* WX  = (float*)(sm + OF_WX);
    float* BB1 = (float*)(sm + OF_BB1);
    float* BB2 = (float*)(sm + OF_BB2);

    // ---- pack weight slices into fp16 mma-fragment order (same as R11) ----
    for (int idx = tid; idx < 16384; idx += NTHREADS) {         // layer 1 (K=128, KTP=8)
        int j = idx & 3, ln = (idx >> 2) & 31, p = (idx >> 7) & 1;
        int ktp = (idx >> 8) & 7, q2 = (idx >> 11) & 1, w = idx >> 12;
        int gate = p * 2 + (j >> 1), reg = j & 1;
        int k0 = ktp * 16 + reg * 8 + 2 * (ln & 3);
        int dim = w * 16 + q2 * 8 + (ln >> 2);
        int gr = gate * HN + rank * 64 + dim;
        __half2 hv = __floats2half2_rn(Whh1[gr * HN + k0], Whh1[gr * HN + k0 + 1]);
        sm[OF_B1 + idx] = *(uint32_t*)&hv;
    }
    for (int idx = tid; idx < 32768; idx += NTHREADS) {         // layer 2 (K=256, KTP=16)
        int j = idx & 3, ln = (idx >> 2) & 31, p = (idx >> 7) & 1;
        int ktp = (idx >> 8) & 15, q2 = (idx >> 12) & 1, w = idx >> 13;
        int gate = p * 2 + (j >> 1), reg = j & 1;
        int k0 = ktp * 16 + reg * 8 + 2 * (ln & 3);
        int dim = w * 16 + q2 * 8 + (ln >> 2);
        int gr = gate * HN + rank * 64 + dim;
        float w0 = (k0 < HN)     ? Wih2[gr * HN + k0]     : Whh2[gr * HN + k0 - HN];
        float w1 = (k0 + 1 < HN) ? Wih2[gr * HN + k0 + 1] : Whh2[gr * HN + k0 + 1 - HN];
        __half2 hv = __floats2half2_rn(w0, w1);
        sm[OF_B2 + idx] = *(uint32_t*)&hv;
    }
    {   // WX / biases: 4 gates x 64 dims
        int gt = tid >> 6, q = tid & 63;
        int gr = gt * HN + rank * 64 + q;
        WX[tid]  = Wih1[gr];
        BB1[tid] = bih1[gr] + bhh1[gr];
        BB2[tid] = bih2[gr] + bhh2[gr];
    }
    for (int i = tid; i < 2 * AWORDS; i += NTHREADS) sm[OF_A + i] = 0u;   // both parities zero
    __syncthreads();
    // publish zeroed A-tiles + weights before any peer DSMEM write/read
    CLUSTER_ARRIVE();
    CLUSTER_WAIT();

    // per-thread rows (2) and ldmatrix offset (single M16 tile)
    int rows[2];
    rows[0] = g;
    rows[1] = g + 8;

    const uint32_t sbA = smem_u32(sm) + OF_A * 4;
    const uint32_t lmoff = (uint32_t)(lane & 15) * 528u + ((lane >> 4) & 1) * 16u;
    // DSMEM write bases: A-tile of CTA0 and CTA1
    const uint32_t dstA0 = mapa_u32(sbA, 0);
    const uint32_t dstA1 = mapa_u32(sbA, 1);

    const uint4* Bq1 = (const uint4*)(sm + OF_B1);
    const uint4* Bq2 = (const uint4*)(sm + OF_B2);

    // WG0 carries c1, WG1 carries c2: 8 cells (2 rows x 2 q2 x 2 qq)
    float cc[8];
#pragma unroll
    for (int i = 0; i < 8; i++) cc[i] = 0.f;

    // write word-column (within 128-word row): h1 -> +0, h2 -> +64
    const int wcol = rank * 32 + lwid * 8 + tq;    // + q2*4 added in loop

    for (int n = 0; n <= SEQT; n++) {
        const uint32_t rbase = sbA + (uint32_t)(n & 1) * ABYTES;         // read parity
        const uint32_t wpar  = (uint32_t)((n + 1) & 1) * ABYTES;         // write parity offset

        if (wg == 0) {
            // ===== layer 1: gates1(t=n) = h1(n-1) @ Whh1^T =====
            if (n < SEQT) {
                float xtv[2];
#pragma unroll
                for (int e = 0; e < 2; e++) xtv[e] = __ldcg(&g_xT[n * BATCH + b0 + rows[e]]);

                float acc[4][2][4];
#pragma unroll
                for (int a1 = 0; a1 < 4; a1++)
#pragma unroll
                    for (int a2 = 0; a2 < 2; a2++)
#pragma unroll
                        for (int a3 = 0; a3 < 4; a3++) acc[a1][a2][a3] = 0.f;

#pragma unroll 2
                for (int ktp = 0; ktp < 8; ktp++) {
                    int base = (lwid * 2) * 8 + ktp;
                    uint4 b0v = Bq1[((base) * 2 + 0) * 32 + lane];
                    uint4 b1v = Bq1[((base) * 2 + 1) * 32 + lane];
                    uint4 b2v = Bq1[((base + 8) * 2 + 0) * 32 + lane];
                    uint4 b3v = Bq1[((base + 8) * 2 + 1) * 32 + lane];
                    uint32_t af[4];
                    ldmA(af, rbase + lmoff + ktp * 32u);
                    mmaf16(acc[0][0], af, b0v.x, b0v.y);
                    mmaf16(acc[1][0], af, b0v.z, b0v.w);
                    mmaf16(acc[2][0], af, b1v.x, b1v.y);
                    mmaf16(acc[3][0], af, b1v.z, b1v.w);
                    mmaf16(acc[0][1], af, b2v.x, b2v.y);
                    mmaf16(acc[1][1], af, b2v.z, b2v.w);
                    mmaf16(acc[2][1], af, b3v.x, b3v.y);
                    mmaf16(acc[3][1], af, b3v.z, b3v.w);
                }
#pragma unroll
                for (int e = 0; e < 2; e++)
#pragma unroll
                    for (int q2 = 0; q2 < 2; q2++) {
                        float hv[2];
#pragma unroll
                        for (int qq = 0; qq < 2; qq++) {
                            int fr = e * 2 + qq;
                            int qloc = lwid * 16 + q2 * 8 + tq * 2 + qq;
                            float gi = acc[0][q2][fr] + xtv[e] * WX[qloc]       + BB1[qloc];
                            float gf = acc[1][q2][fr] + xtv[e] * WX[64 + qloc]  + BB1[64 + qloc];
                            float gg = acc[2][q2][fr] + xtv[e] * WX[128 + qloc] + BB1[128 + qloc];
                            float go = acc[3][q2][fr] + xtv[e] * WX[192 + qloc] + BB1[192 + qloc];
                            float iv = sigfa(gi), fv = sigfa(gf), gv = tanha(gg), ov = sigfa(go);
                            int ci = e * 4 + q2 * 2 + qq;
                            cc[ci] = fv * cc[ci] + iv * gv;
                            hv[qq] = ov * tanha(cc[ci]);
                        }
                        __half2 hp = __floats2half2_rn(hv[0], hv[1]);
                        uint32_t v = *(uint32_t*)&hp;
                        uint32_t boff = wpar + (uint32_t)(rows[e] * SAW + wcol + q2 * 4) * 4u;
                        STSC(dstA0 + boff, v);
                        STSC(dstA1 + boff, v);
                    }
            }
        } else {
            // ===== layer 2: gates2(t=n-1) = [h1(n-1)|h2(n-2)] @ [Wih2|Whh2]^T =====
            if (n > 0) {
                float acc[4][2][4];
#pragma unroll
                for (int a1 = 0; a1 < 4; a1++)
#pragma unroll
                    for (int a2 = 0; a2 < 2; a2++)
#pragma unroll
                        for (int a3 = 0; a3 < 4; a3++) acc[a1][a2][a3] = 0.f;

#pragma unroll 2
                for (int ktp = 0; ktp < 16; ktp++) {
                    int base = (lwid * 2) * 16 + ktp;
                    uint4 b0v = Bq2[((base) * 2 + 0) * 32 + lane];
                    uint4 b1v = Bq2[((base) * 2 + 1) * 32 + lane];
                    uint4 b2v = Bq2[((base + 16) * 2 + 0) * 32 + lane];
                    uint4 b3v = Bq2[((base + 16) * 2 + 1) * 32 + lane];
                    uint32_t af[4];
                    ldmA(af, rbase + lmoff + ktp * 32u);
                    mmaf16(acc[0][0], af, b0v.x, b0v.y);
                    mmaf16(acc[1][0], af, b0v.z, b0v.w);
                    mmaf16(acc[2][0], af, b1v.x, b1v.y);
                    mmaf16(acc[3][0], af, b1v.z, b1v.w);
                    mmaf16(acc[0][1], af, b2v.x, b2v.y);
                    mmaf16(acc[1][1], af, b2v.z, b2v.w);
                    mmaf16(acc[2][1], af, b3v.x, b3v.y);
                    mmaf16(acc[3][1], af, b3v.z, b3v.w);
                }
#pragma unroll
                for (int e = 0; e < 2; e++)
#pragma unroll
                    for (int q2 = 0; q2 < 2; q2++) {
                        float hv[2];
#pragma unroll
                        for (int qq = 0; qq < 2; qq++) {
                            int fr = e * 2 + qq;
                            int qloc = lwid * 16 + q2 * 8 + tq * 2 + qq;
                            float gi = acc[0][q2][fr] + BB2[qloc];
                            float gf = acc[1][q2][fr] + BB2[64 + qloc];
                            float gg = acc[2][q2][fr] + BB2[128 + qloc];
                            float go = acc[3][q2][fr] + BB2[192 + qloc];
                            float iv = sigfa(gi), fv = sigfa(gf), gv = tanha(gg), ov = sigfa(go);
                            int ci = e * 4 + q2 * 2 + qq;
                            cc[ci] = fv * cc[ci] + iv * gv;
                            hv[qq] = ov * tanha(cc[ci]);
                        }
                        __half2 hp = __floats2half2_rn(hv[0], hv[1]);
                        uint32_t v = *(uint32_t*)&hp;
                        uint32_t boff = wpar + (uint32_t)(rows[e] * SAW + 64 + wcol + q2 * 4) * 4u;
                        STSC(dstA0 + boff, v);
                        STSC(dstA1 + boff, v);
                    }
            }
            // n == 0: h2(-1) = 0 already in pre-zeroed buffers
        }

        // one cluster barrier per step: orders both CTAs' DSMEM stores
        // (release on arrive) against next iteration's ldmatrix reads (acquire on wait)
        CLUSTER_ARRIVE();
        CLUSTER_WAIT();
    }

    // ---- final linear: out[b] = h2[b,:] . Wl + bl ----
    // h2(SEQT-1) sits in A buffer parity (SEQT+1)&1, words 64..127 of each row (local smem)
    if (rank == 0 && tid < MROWS) {
        const uint32_t* hr = sm + OF_A + ((SEQT + 1) & 1) * AWORDS + tid * SAW + 64;
        float acc = bl[0];
#pragma unroll 16
        for (int w = 0; w < 64; w++) {
            uint32_t u = hr[w];
            float2 f = __half22float2(*(__half2*)&u);
            acc += f.x * Wl[2 * w] + f.y * Wl[2 * w + 1];
        }
        out[b0 + tid] = acc;
    }
    // keep both CTAs resident until peer reads of DSMEM are impossible
    CLUSTER_ARRIVE();
    CLUSTER_WAIT();
}

// ======================= launch =======================
extern "C" void kernel_launch(void* const* d_in, const int* in_sizes, int n_in,
                              void* d_out, int out_size) {
    const float* x    = (const float*)d_in[0];
    const float* Wih1 = (const float*)d_in[1];
    const float* Whh1 = (const float*)d_in[2];
    const float* bih1 = (const float*)d_in[3];
    const float* bhh1 = (const float*)d_in[4];
    const float* Wih2 = (const float*)d_in[5];
    const float* Whh2 = (const float*)d_in[6];
    const float* bih2 = (const float*)d_in[7];
    const float* bhh2 = (const float*)d_in[8];
    const float* Wl   = (const float*)d_in[9];
    const float* bl   = (const float*)d_in[10];
    float* out = (float*)d_out;

    cudaFuncSetAttribute(lstm2_kernel, cudaFuncAttributeMaxDynamicSharedMemorySize, SMEM_BYTES);

    xT_kernel<<<(BATCH * SEQT + 255) / 256, 256>>>(x);
    lstm2_kernel<<<(BATCH / MROWS) * CL, NTHREADS, SMEM_BYTES>>>(
        Wih1, Whh1, bih1, bhh1, Wih2, Whh2, bih2, bhh2, Wl, bl, out);
}

// round 14
// speedup vs baseline: 3.8550x; 1.0881x over previous
#include <cuda_runtime.h>
#include <cuda_fp16.h>
#include <cstdint>

#define HN       128
#define BATCH    1024
#define SEQT     512
#define CL       2            // CTAs per cluster
#define MROWS    16           // batch rows per cluster
#define NTHREADS 256

#define SAW      132          // A-tile row stride in 32-bit words (264 fp16 = 528 B)
#define AWORDS   (MROWS * SAW)           // 2112 words per A buffer
#define ABYTES   (AWORDS * 4)            // 8448 B

// ---- shared memory layout (32-bit word offsets) ----
#define OF_A     0                       // A tiles x2 (parity) = 4224 words
#define OF_B1    (2 * AWORDS)            // layer-1 B frags: 16384 words (64 KB)
#define OF_B2    (OF_B1 + 16384)         // layer-2 B frags: 32768 words (128 KB)
#define OF_WX    (OF_B2 + 32768)         // Wih1 slice   [256] floats (4 gates x 64 dims)
#define OF_BB1   (OF_WX + 256)           // bih1+bhh1    [256] floats
#define OF_BB2   (OF_BB1 + 256)          // bih2+bhh2    [256] floats
#define SMEM_WORDS (OF_BB2 + 256)
#define SMEM_BYTES (SMEM_WORDS * 4)      // 216,576 B

// ---- device scratch (allocation-free) ----
__device__ float g_xT[SEQT * BATCH];     // x transposed to [T, B]

// ======================= helpers =======================
__device__ __forceinline__ uint32_t smem_u32(const void* p) {
    uint32_t a;
    asm("{ .reg .u64 t; cvta.to.shared.u64 t, %1; cvt.u32.u64 %0, t; }" : "=r"(a) : "l"(p));
    return a;
}
__device__ __forceinline__ uint32_t mapa_u32(uint32_t addr, int r) {
    uint32_t o;
    asm("mapa.shared::cluster.u32 %0, %1, %2;" : "=r"(o) : "r"(addr), "r"(r));
    return o;
}
#define CLUSTER_ARRIVE() asm volatile("barrier.cluster.arrive.aligned;" ::: "memory")
#define CLUSTER_WAIT()   asm volatile("barrier.cluster.wait.aligned;" ::: "memory")
#define STSC(addr, v)    asm volatile("st.shared::cluster.u32 [%0], %1;" :: "r"(addr), "r"(v) : "memory")

__device__ __forceinline__ void mmaf16(float* d, const uint32_t* a, uint32_t b0, uint32_t b1) {
    asm volatile(
        "mma.sync.aligned.m16n8k16.row.col.f32.f16.f16.f32 "
        "{%0,%1,%2,%3}, {%4,%5,%6,%7}, {%8,%9}, {%0,%1,%2,%3};"
        : "+f"(d[0]), "+f"(d[1]), "+f"(d[2]), "+f"(d[3])
        : "r"(a[0]), "r"(a[1]), "r"(a[2]), "r"(a[3]), "r"(b0), "r"(b1));
}
__device__ __forceinline__ void ldmA(uint32_t* r, uint32_t addr) {
    asm volatile("ldmatrix.sync.aligned.m8n8.x4.shared.b16 {%0,%1,%2,%3}, [%4];"
                 : "=r"(r[0]), "=r"(r[1]), "=r"(r[2]), "=r"(r[3]) : "r"(addr));
}
// full-approx activations (validated: rel_err 4.64e-4)
__device__ __forceinline__ float tanha(float x) {
    float y; asm("tanh.approx.f32 %0, %1;" : "=f"(y) : "f"(x)); return y;
}
__device__ __forceinline__ float sigfa(float x) {
    return fmaf(0.5f, tanha(0.5f * x), 0.5f);
}

// ======================= kernels =======================
__global__ void xT_kernel(const float* __restrict__ x) {
    int i = blockIdx.x * blockDim.x + threadIdx.x;   // i = t*1024 + b (coalesced writes)
    if (i < BATCH * SEQT) {
        int tt = i >> 10, b = i & 1023;
        g_xT[i] = x[b * SEQT + tt];
    }
}

extern "C" __global__ void __launch_bounds__(NTHREADS, 1) __cluster_dims__(CL, 1, 1)
lstm2_kernel(const float* __restrict__ Wih1, const float* __restrict__ Whh1,
             const float* __restrict__ bih1, const float* __restrict__ bhh1,
             const float* __restrict__ Wih2, const float* __restrict__ Whh2,
             const float* __restrict__ bih2, const float* __restrict__ bhh2,
             const float* __restrict__ Wl,   const float* __restrict__ bl,
             float* __restrict__ out)
{
    extern __shared__ uint32_t sm[];
    const int tid  = threadIdx.x;
    const int lane = tid & 31;
    const int wid  = tid >> 5;          // 0..7
    const int wg   = wid >> 2;          // 0 = layer-1 group, 1 = layer-2 group
    const int lwid = wid & 3;           // warp within group -> 16-dim slice
    const int g    = lane >> 2;
    const int tq   = lane & 3;
    const int rank = blockIdx.x & (CL - 1);
    const int b0   = (blockIdx.x / CL) * MROWS;

    float* WX  = (float*)(sm + OF_WX);
    float* BB1 = (float*)(sm + OF_BB1);
    float* BB2 = (float*)(sm + OF_BB2);

    // ---- pack weight slices into fp16 mma-fragment order (same as R13) ----
    for (int idx = tid; idx < 16384; idx += NTHREADS) {         // layer 1 (K=128, KTP=8)
        int j = idx & 3, ln = (idx >> 2) & 31, p = (idx >> 7) & 1;
        int ktp = (idx >> 8) & 7, q2 = (idx >> 11) & 1, w = idx >> 12;
        int gate = p * 2 + (j >> 1), reg = j & 1;
        int k0 = ktp * 16 + reg * 8 + 2 * (ln & 3);
        int dim = w * 16 + q2 * 8 + (ln >> 2);
        int gr = gate * HN + rank * 64 + dim;
        __half2 hv = __floats2half2_rn(Whh1[gr * HN + k0], Whh1[gr * HN + k0 + 1]);
        sm[OF_B1 + idx] = *(uint32_t*)&hv;
    }
    for (int idx = tid; idx < 32768; idx += NTHREADS) {         // layer 2 (K=256, KTP=16)
        int j = idx & 3, ln = (idx >> 2) & 31, p = (idx >> 7) & 1;
        int ktp = (idx >> 8) & 15, q2 = (idx >> 12) & 1, w = idx >> 13;
        int gate = p * 2 + (j >> 1), reg = j & 1;
        int k0 = ktp * 16 + reg * 8 + 2 * (ln & 3);
        int dim = w * 16 + q2 * 8 + (ln >> 2);
        int gr = gate * HN + rank * 64 + dim;
        float w0 = (k0 < HN)     ? Wih2[gr * HN + k0]     : Whh2[gr * HN + k0 - HN];
        float w1 = (k0 + 1 < HN) ? Wih2[gr * HN + k0 + 1] : Whh2[gr * HN + k0 + 1 - HN];
        __half2 hv = __floats2half2_rn(w0, w1);
        sm[OF_B2 + idx] = *(uint32_t*)&hv;
    }
    {   // WX / biases: 4 gates x 64 dims
        int gt = tid >> 6, q = tid & 63;
        int gr = gt * HN + rank * 64 + q;
        WX[tid]  = Wih1[gr];
        BB1[tid] = bih1[gr] + bhh1[gr];
        BB2[tid] = bih2[gr] + bhh2[gr];
    }
    for (int i = tid; i < 2 * AWORDS; i += NTHREADS) sm[OF_A + i] = 0u;   // both parities zero
    __syncthreads();
    // publish zeroed A-tiles + weights before any peer DSMEM write/read
    CLUSTER_ARRIVE();
    CLUSTER_WAIT();

    // per-thread rows (2) and ldmatrix offset (single M16 tile)
    int rows[2];
    rows[0] = g;
    rows[1] = g + 8;

    const uint32_t sbA = smem_u32(sm) + OF_A * 4;
    const uint32_t lmoff = (uint32_t)(lane & 15) * 528u + ((lane >> 4) & 1) * 16u;
    // DSMEM write bases: A-tile of CTA0 and CTA1
    const uint32_t dstA0 = mapa_u32(sbA, 0);
    const uint32_t dstA1 = mapa_u32(sbA, 1);

    const uint4* Bq1 = (const uint4*)(sm + OF_B1);
    const uint4* Bq2 = (const uint4*)(sm + OF_B2);

    // ---- hoist loop-invariant B fragments into registers ----
    // WG0: all 8 ktp (32 uint4). WG1: ktp 0..7 (32 uint4); ktp 8..15 stay in smem.
    uint4 bh[32];
    if (wg == 0) {
#pragma unroll
        for (int ktp = 0; ktp < 8; ktp++) {
            int base = (lwid * 2) * 8 + ktp;
            bh[ktp * 4 + 0] = Bq1[((base) * 2 + 0) * 32 + lane];
            bh[ktp * 4 + 1] = Bq1[((base) * 2 + 1) * 32 + lane];
            bh[ktp * 4 + 2] = Bq1[((base + 8) * 2 + 0) * 32 + lane];
            bh[ktp * 4 + 3] = Bq1[((base + 8) * 2 + 1) * 32 + lane];
        }
    } else {
#pragma unroll
        for (int ktp = 0; ktp < 8; ktp++) {
            int base = (lwid * 2) * 16 + ktp;
            bh[ktp * 4 + 0] = Bq2[((base) * 2 + 0) * 32 + lane];
            bh[ktp * 4 + 1] = Bq2[((base) * 2 + 1) * 32 + lane];
            bh[ktp * 4 + 2] = Bq2[((base + 16) * 2 + 0) * 32 + lane];
            bh[ktp * 4 + 3] = Bq2[((base + 16) * 2 + 1) * 32 + lane];
        }
    }
    // ---- hoist epilogue constants (per-thread slice of WX / biases) ----
    float wxv[16], bbv[16];
    {
        const float* Wt = (wg == 0) ? WX : 0;
        const float* Bt = (wg == 0) ? BB1 : BB2;
#pragma unroll
        for (int gate = 0; gate < 4; gate++)
#pragma unroll
            for (int q2 = 0; q2 < 2; q2++)
#pragma unroll
                for (int qq = 0; qq < 2; qq++) {
                    int qloc = lwid * 16 + q2 * 8 + tq * 2 + qq;
                    int ii = gate * 4 + q2 * 2 + qq;
                    bbv[ii] = Bt[gate * 64 + qloc];
                    wxv[ii] = (wg == 0) ? Wt[gate * 64 + qloc] : 0.f;
                }
    }

    // WG0 carries c1, WG1 carries c2: 8 cells (2 rows x 2 q2 x 2 qq)
    float cc[8];
#pragma unroll
    for (int i = 0; i < 8; i++) cc[i] = 0.f;

    // write word-column (within 128-word row): h1 -> +0, h2 -> +64
    const int wcol = rank * 32 + lwid * 8 + tq;    // + q2*4 added in loop

    // initial x prefetch (t=0)
    float xtv[2];
    if (wg == 0) {
#pragma unroll
        for (int e = 0; e < 2; e++) xtv[e] = __ldcg(&g_xT[0 * BATCH + b0 + rows[e]]);
    }

    for (int n = 0; n <= SEQT; n++) {
        const uint32_t rbase = sbA + (uint32_t)(n & 1) * ABYTES;         // read parity
        const uint32_t wpar  = (uint32_t)((n + 1) & 1) * ABYTES;         // write parity offset

        // wait pairs with previous iteration's arrive (n=0 covered by setup sync)
        if (n > 0) CLUSTER_WAIT();

        if (wg == 0) {
            // ===== layer 1: gates1(t=n) = h1(n-1) @ Whh1^T =====
            if (n < SEQT) {
                float acc[4][2][4];
#pragma unroll
                for (int a1 = 0; a1 < 4; a1++)
#pragma unroll
                    for (int a2 = 0; a2 < 2; a2++)
#pragma unroll
                        for (int a3 = 0; a3 < 4; a3++) acc[a1][a2][a3] = 0.f;

#pragma unroll
                for (int ktp = 0; ktp < 8; ktp++) {
                    uint32_t af[4];
                    ldmA(af, rbase + lmoff + ktp * 32u);
                    mmaf16(acc[0][0], af, bh[ktp * 4 + 0].x, bh[ktp * 4 + 0].y);
                    mmaf16(acc[1][0], af, bh[ktp * 4 + 0].z, bh[ktp * 4 + 0].w);
                    mmaf16(acc[2][0], af, bh[ktp * 4 + 1].x, bh[ktp * 4 + 1].y);
                    mmaf16(acc[3][0], af, bh[ktp * 4 + 1].z, bh[ktp * 4 + 1].w);
                    mmaf16(acc[0][1], af, bh[ktp * 4 + 2].x, bh[ktp * 4 + 2].y);
                    mmaf16(acc[1][1], af, bh[ktp * 4 + 2].z, bh[ktp * 4 + 2].w);
                    mmaf16(acc[2][1], af, bh[ktp * 4 + 3].x, bh[ktp * 4 + 3].y);
                    mmaf16(acc[3][1], af, bh[ktp * 4 + 3].z, bh[ktp * 4 + 3].w);
                }
#pragma unroll
                for (int e = 0; e < 2; e++)
#pragma unroll
                    for (int q2 = 0; q2 < 2; q2++) {
                        float hv[2];
#pragma unroll
                        for (int qq = 0; qq < 2; qq++) {
                            int fr = e * 2 + qq;
                            int ii = q2 * 2 + qq;
                            float gi = acc[0][q2][fr] + xtv[e] * wxv[ii]      + bbv[ii];
                            float gf = acc[1][q2][fr] + xtv[e] * wxv[4 + ii]  + bbv[4 + ii];
                            float gg = acc[2][q2][fr] + xtv[e] * wxv[8 + ii]  + bbv[8 + ii];
                            float go = acc[3][q2][fr] + xtv[e] * wxv[12 + ii] + bbv[12 + ii];
                            float iv = sigfa(gi), fv = sigfa(gf), gv = tanha(gg), ov = sigfa(go);
                            int ci = e * 4 + q2 * 2 + qq;
                            cc[ci] = fv * cc[ci] + iv * gv;
                            hv[qq] = ov * tanha(cc[ci]);
                        }
                        __half2 hp = __floats2half2_rn(hv[0], hv[1]);
                        uint32_t v = *(uint32_t*)&hp;
                        uint32_t boff = wpar + (uint32_t)(rows[e] * SAW + wcol + q2 * 4) * 4u;
                        STSC(dstA0 + boff, v);
                        STSC(dstA1 + boff, v);
                    }
            }
        } else {
            // ===== layer 2: gates2(t=n-1) = [h1(n-1)|h2(n-2)] @ [Wih2|Whh2]^T =====
            if (n > 0) {
                float acc[4][2][4];
#pragma unroll
                for (int a1 = 0; a1 < 4; a1++)
#pragma unroll
                    for (int a2 = 0; a2 < 2; a2++)
#pragma unroll
                        for (int a3 = 0; a3 < 4; a3++) acc[a1][a2][a3] = 0.f;

                // ktp 0..7 from hoisted regs
#pragma unroll
                for (int ktp = 0; ktp < 8; ktp++) {
                    uint32_t af[4];
                    ldmA(af, rbase + lmoff + ktp * 32u);
                    mmaf16(acc[0][0], af, bh[ktp * 4 + 0].x, bh[ktp * 4 + 0].y);
                    mmaf16(acc[1][0], af, bh[ktp * 4 + 0].z, bh[ktp * 4 + 0].w);
                    mmaf16(acc[2][0], af, bh[ktp * 4 + 1].x, bh[ktp * 4 + 1].y);
                    mmaf16(acc[3][0], af, bh[ktp * 4 + 1].z, bh[ktp * 4 + 1].w);
                    mmaf16(acc[0][1], af, bh[ktp * 4 + 2].x, bh[ktp * 4 + 2].y);
                    mmaf16(acc[1][1], af, bh[ktp * 4 + 2].z, bh[ktp * 4 + 2].w);
                    mmaf16(acc[2][1], af, bh[ktp * 4 + 3].x, bh[ktp * 4 + 3].y);
                    mmaf16(acc[3][1], af, bh[ktp * 4 + 3].z, bh[ktp * 4 + 3].w);
                }
                // ktp 8..15 from smem
#pragma unroll 2
                for (int ktp = 8; ktp < 16; ktp++) {
                    int base = (lwid * 2) * 16 + ktp;
                    uint4 b0v = Bq2[((base) * 2 + 0) * 32 + lane];
                    uint4 b1v = Bq2[((base) * 2 + 1) * 32 + lane];
                    uint4 b2v = Bq2[((base + 16) * 2 + 0) * 32 + lane];
                    uint4 b3v = Bq2[((base + 16) * 2 + 1) * 32 + lane];
                    uint32_t af[4];
                    ldmA(af, rbase + lmoff + ktp * 32u);
                    mmaf16(acc[0][0], af, b0v.x, b0v.y);
                    mmaf16(acc[1][0], af, b0v.z, b0v.w);
                    mmaf16(acc[2][0], af, b1v.x, b1v.y);
                    mmaf16(acc[3][0], af, b1v.z, b1v.w);
                    mmaf16(acc[0][1], af, b2v.x, b2v.y);
                    mmaf16(acc[1][1], af, b2v.z, b2v.w);
                    mmaf16(acc[2][1], af, b3v.x, b3v.y);
                    mmaf16(acc[3][1], af, b3v.z, b3v.w);
                }
#pragma unroll
                for (int e = 0; e < 2; e++)
#pragma unroll
                    for (int q2 = 0; q2 < 2; q2++) {
                        float hv[2];
#pragma unroll
                        for (int qq = 0; qq < 2; qq++) {
                            int fr = e * 2 + qq;
                            int ii = q2 * 2 + qq;
                            float gi = acc[0][q2][fr] + bbv[ii];
                            float gf = acc[1][q2][fr] + bbv[4 + ii];
                            float gg = acc[2][q2][fr] + bbv[8 + ii];
                            float go = acc[3][q2][fr] + bbv[12 + ii];
                            float iv = sigfa(gi), fv = sigfa(gf), gv = tanha(gg), ov = sigfa(go);
                            int ci = e * 4 + q2 * 2 + qq;
                            cc[ci] = fv * cc[ci] + iv * gv;
                            hv[qq] = ov * tanha(cc[ci]);
                        }
                        __half2 hp = __floats2half2_rn(hv[0], hv[1]);
                        uint32_t v = *(uint32_t*)&hp;
                        uint32_t boff = wpar + (uint32_t)(rows[e] * SAW + 64 + wcol + q2 * 4) * 4u;
                        STSC(dstA0 + boff, v);
                        STSC(dstA1 + boff, v);
                    }
            }
            // n == 0: h2(-1) = 0 already in pre-zeroed buffers
        }

        // release this iteration's DSMEM stores; overlap the barrier with x prefetch
        CLUSTER_ARRIVE();
        if (wg == 0 && n + 1 < SEQT) {
#pragma unroll
            for (int e = 0; e < 2; e++) xtv[e] = __ldcg(&g_xT[(n + 1) * BATCH + b0 + rows[e]]);
        }
    }

    // final wait pairs with last iteration's arrive; then h2 halves from peer are visible
    CLUSTER_WAIT();

    // ---- final linear: out[b] = h2[b,:] . Wl + bl ----
    // h2(SEQT-1) sits in A buffer parity (SEQT+1)&1, words 64..127 of each row (local smem)
    if (rank == 0 && tid < MROWS) {
        const uint32_t* hr = sm + OF_A + ((SEQT + 1) & 1) * AWORDS + tid * SAW + 64;
        float acc = bl[0];
#pragma unroll 16
        for (int w = 0; w < 64; w++) {
            uint32_t u = hr[w];
            float2 f = __half22float2(*(__half2*)&u);
            acc += f.x * Wl[2 * w] + f.y * Wl[2 * w + 1];
        }
        out[b0 + tid] = acc;
    }
    // keep both CTAs resident until peer reads of DSMEM are impossible
    CLUSTER_ARRIVE();
    CLUSTER_WAIT();
}

// ======================= launch =======================
extern "C" void kernel_launch(void* const* d_in, const int* in_sizes, int n_in,
                              void* d_out, int out_size) {
    const float* x    = (const float*)d_in[0];
    const float* Wih1 = (const float*)d_in[1];
    const float* Whh1 = (const float*)d_in[2];
    const float* bih1 = (const float*)d_in[3];
    const float* bhh1 = (const float*)d_in[4];
    const float* Wih2 = (const float*)d_in[5];
    const float* Whh2 = (const float*)d_in[6];
    const float* bih2 = (const float*)d_in[7];
    const float* bhh2 = (const float*)d_in[8];
    const float* Wl   = (const float*)d_in[9];
    const float* bl   = (const float*)d_in[10];
    float* out = (float*)d_out;

    cudaFuncSetAttribute(lstm2_kernel, cudaFuncAttributeMaxDynamicSharedMemorySize, SMEM_BYTES);

    xT_kernel<<<(BATCH * SEQT + 255) / 256, 256>>>(x);
    lstm2_kernel<<<(BATCH / MROWS) * CL, NTHREADS, SMEM_BYTES>>>(
        Wih1, Whh1, bih1, bhh1, Wih2, Whh2, bih2, bhh2, Wl, bl, out);
}

// round 15
// speedup vs baseline: 3.8970x; 1.0109x over previous
#include <cuda_runtime.h>
#include <cuda_fp16.h>
#include <cstdint>

#define HN       128
#define BATCH    1024
#define SEQT     512
#define CL       2            // CTAs per cluster
#define MROWS    16           // batch rows per cluster
#define NTHREADS 256

#define SAW      132          // A-tile row stride in 32-bit words (264 fp16 = 528 B)
#define AWORDS   (MROWS * SAW)           // 2112 words per A buffer
#define ABYTES   (AWORDS * 4)            // 8448 B

// ---- shared memory layout (32-bit word offsets) ----
#define OF_A     0                       // A tiles x2 (parity) = 4224 words
#define OF_B1    (2 * AWORDS)            // layer-1 B frags: 16384 words (64 KB)
#define OF_B2    (OF_B1 + 16384)         // layer-2 B frags: 32768 words (128 KB)
#define OF_WX    (OF_B2 + 32768)         // Wih1 slice   [256] floats (4 gates x 64 dims)
#define OF_BB1   (OF_WX + 256)           // bih1+bhh1    [256] floats
#define OF_BB2   (OF_BB1 + 256)          // bih2+bhh2    [256] floats
#define SMEM_WORDS (OF_BB2 + 256)
#define SMEM_BYTES (SMEM_WORDS * 4)      // 216,576 B

// ---- device scratch (allocation-free) ----
__device__ float g_xT[SEQT * BATCH];     // x transposed to [T, B]

// ======================= helpers =======================
__device__ __forceinline__ uint32_t smem_u32(const void* p) {
    uint32_t a;
    asm("{ .reg .u64 t; cvta.to.shared.u64 t, %1; cvt.u32.u64 %0, t; }" : "=r"(a) : "l"(p));
    return a;
}
__device__ __forceinline__ uint32_t mapa_u32(uint32_t addr, int r) {
    uint32_t o;
    asm("mapa.shared::cluster.u32 %0, %1, %2;" : "=r"(o) : "r"(addr), "r"(r));
    return o;
}
#define CLUSTER_ARRIVE() asm volatile("barrier.cluster.arrive.aligned;" ::: "memory")
#define CLUSTER_WAIT()   asm volatile("barrier.cluster.wait.aligned;" ::: "memory")
#define STSC(addr, v)    asm volatile("st.shared::cluster.u32 [%0], %1;" :: "r"(addr), "r"(v) : "memory")
#define STSL(addr, v)    asm volatile("st.shared.u32 [%0], %1;" :: "r"(addr), "r"(v) : "memory")

__device__ __forceinline__ void mmaf16(float* d, const uint32_t* a, uint32_t b0, uint32_t b1) {
    asm volatile(
        "mma.sync.aligned.m16n8k16.row.col.f32.f16.f16.f32 "
        "{%0,%1,%2,%3}, {%4,%5,%6,%7}, {%8,%9}, {%0,%1,%2,%3};"
        : "+f"(d[0]), "+f"(d[1]), "+f"(d[2]), "+f"(d[3])
        : "r"(a[0]), "r"(a[1]), "r"(a[2]), "r"(a[3]), "r"(b0), "r"(b1));
}
__device__ __forceinline__ void ldmA(uint32_t* r, uint32_t addr) {
    asm volatile("ldmatrix.sync.aligned.m8n8.x4.shared.b16 {%0,%1,%2,%3}, [%4];"
                 : "=r"(r[0]), "=r"(r[1]), "=r"(r[2]), "=r"(r[3]) : "r"(addr));
}
// full-approx activations (validated: rel_err 4.64e-4)
__device__ __forceinline__ float tanha(float x) {
    float y; asm("tanh.approx.f32 %0, %1;" : "=f"(y) : "f"(x)); return y;
}
__device__ __forceinline__ float sigfa(float x) {
    return fmaf(0.5f, tanha(0.5f * x), 0.5f);
}

// ======================= kernels =======================
__global__ void xT_kernel(const float* __restrict__ x) {
    int i = blockIdx.x * blockDim.x + threadIdx.x;   // i = t*1024 + b (coalesced writes)
    if (i < BATCH * SEQT) {
        int tt = i >> 10, b = i & 1023;
        g_xT[i] = x[b * SEQT + tt];
    }
}

extern "C" __global__ void __launch_bounds__(NTHREADS, 1) __cluster_dims__(CL, 1, 1)
lstm2_kernel(const float* __restrict__ Wih1, const float* __restrict__ Whh1,
             const float* __restrict__ bih1, const float* __restrict__ bhh1,
             const float* __restrict__ Wih2, const float* __restrict__ Whh2,
             const float* __restrict__ bih2, const float* __restrict__ bhh2,
             const float* __restrict__ Wl,   const float* __restrict__ bl,
             float* __restrict__ out)
{
    extern __shared__ uint32_t sm[];
    const int tid  = threadIdx.x;
    const int lane = tid & 31;
    const int wid  = tid >> 5;          // 0..7
    const int wg   = wid >> 2;          // 0 = layer-1 group, 1 = layer-2 group
    const int lwid = wid & 3;           // warp within group -> 16-dim slice
    const int g    = lane >> 2;
    const int tq   = lane & 3;
    const int rank = blockIdx.x & (CL - 1);
    const int b0   = (blockIdx.x / CL) * MROWS;

    float* WX  = (float*)(sm + OF_WX);
    float* BB1 = (float*)(sm + OF_BB1);
    float* BB2 = (float*)(sm + OF_BB2);

    // ---- pack weight slices into fp16 mma-fragment order (same as R14) ----
    for (int idx = tid; idx < 16384; idx += NTHREADS) {         // layer 1 (K=128, KTP=8)
        int j = idx & 3, ln = (idx >> 2) & 31, p = (idx >> 7) & 1;
        int ktp = (idx >> 8) & 7, q2 = (idx >> 11) & 1, w = idx >> 12;
        int gate = p * 2 + (j >> 1), reg = j & 1;
        int k0 = ktp * 16 + reg * 8 + 2 * (ln & 3);
        int dim = w * 16 + q2 * 8 + (ln >> 2);
        int gr = gate * HN + rank * 64 + dim;
        __half2 hv = __floats2half2_rn(Whh1[gr * HN + k0], Whh1[gr * HN + k0 + 1]);
        sm[OF_B1 + idx] = *(uint32_t*)&hv;
    }
    for (int idx = tid; idx < 32768; idx += NTHREADS) {         // layer 2 (K=256, KTP=16)
        int j = idx & 3, ln = (idx >> 2) & 31, p = (idx >> 7) & 1;
        int ktp = (idx >> 8) & 15, q2 = (idx >> 12) & 1, w = idx >> 13;
        int gate = p * 2 + (j >> 1), reg = j & 1;
        int k0 = ktp * 16 + reg * 8 + 2 * (ln & 3);
        int dim = w * 16 + q2 * 8 + (ln >> 2);
        int gr = gate * HN + rank * 64 + dim;
        float w0 = (k0 < HN)     ? Wih2[gr * HN + k0]     : Whh2[gr * HN + k0 - HN];
        float w1 = (k0 + 1 < HN) ? Wih2[gr * HN + k0 + 1] : Whh2[gr * HN + k0 + 1 - HN];
        __half2 hv = __floats2half2_rn(w0, w1);
        sm[OF_B2 + idx] = *(uint32_t*)&hv;
    }
    {   // WX / biases: 4 gates x 64 dims
        int gt = tid >> 6, q = tid & 63;
        int gr = gt * HN + rank * 64 + q;
        WX[tid]  = Wih1[gr];
        BB1[tid] = bih1[gr] + bhh1[gr];
        BB2[tid] = bih2[gr] + bhh2[gr];
    }
    for (int i = tid; i < 2 * AWORDS; i += NTHREADS) sm[OF_A + i] = 0u;   // both parities zero
    __syncthreads();
    // publish zeroed A-tiles + weights before any peer DSMEM write/read
    CLUSTER_ARRIVE();
    CLUSTER_WAIT();

    // per-thread rows (2) and ldmatrix offset (single M16 tile)
    int rows[2];
    rows[0] = g;
    rows[1] = g + 8;

    const uint32_t sbA = smem_u32(sm) + OF_A * 4;
    const uint32_t lmoff = (uint32_t)(lane & 15) * 528u + ((lane >> 4) & 1) * 16u;
    // DSMEM write base: peer CTA's A-tile only (local goes via plain STS)
    const uint32_t dstPeer = mapa_u32(sbA, rank ^ 1);

    const uint4* Bq1 = (const uint4*)(sm + OF_B1);
    const uint4* Bq2 = (const uint4*)(sm + OF_B2);

    // ---- hoist loop-invariant B fragments into registers ----
    // WG0: all 8 ktp (32 uint4). WG1: ktp 0..7 (32 uint4); ktp 8..15 stay in smem.
    uint4 bh[32];
    if (wg == 0) {
#pragma unroll
        for (int ktp = 0; ktp < 8; ktp++) {
            int base = (lwid * 2) * 8 + ktp;
            bh[ktp * 4 + 0] = Bq1[((base) * 2 + 0) * 32 + lane];
            bh[ktp * 4 + 1] = Bq1[((base) * 2 + 1) * 32 + lane];
            bh[ktp * 4 + 2] = Bq1[((base + 8) * 2 + 0) * 32 + lane];
            bh[ktp * 4 + 3] = Bq1[((base + 8) * 2 + 1) * 32 + lane];
        }
    } else {
#pragma unroll
        for (int ktp = 0; ktp < 8; ktp++) {
            int base = (lwid * 2) * 16 + ktp;
            bh[ktp * 4 + 0] = Bq2[((base) * 2 + 0) * 32 + lane];
            bh[ktp * 4 + 1] = Bq2[((base) * 2 + 1) * 32 + lane];
            bh[ktp * 4 + 2] = Bq2[((base + 16) * 2 + 0) * 32 + lane];
            bh[ktp * 4 + 3] = Bq2[((base + 16) * 2 + 1) * 32 + lane];
        }
    }
    // ---- hoist epilogue constants (per-thread slice of WX / biases) ----
    float wxv[16], bbv[16];
    {
        const float* Wt = (wg == 0) ? WX : 0;
        const float* Bt = (wg == 0) ? BB1 : BB2;
#pragma unroll
        for (int gate = 0; gate < 4; gate++)
#pragma unroll
            for (int q2 = 0; q2 < 2; q2++)
#pragma unroll
                for (int qq = 0; qq < 2; qq++) {
                    int qloc = lwid * 16 + q2 * 8 + tq * 2 + qq;
                    int ii = gate * 4 + q2 * 2 + qq;
                    bbv[ii] = Bt[gate * 64 + qloc];
                    wxv[ii] = (wg == 0) ? Wt[gate * 64 + qloc] : 0.f;
                }
    }

    // WG0 carries c1, WG1 carries c2: 8 cells (2 rows x 2 q2 x 2 qq)
    float cc[8];
#pragma unroll
    for (int i = 0; i < 8; i++) cc[i] = 0.f;

    // write word-column (within 128-word row): h1 -> +0, h2 -> +64
    const int wcol = rank * 32 + lwid * 8 + tq;    // + q2*4 added in loop

    // initial x prefetch (t=0)
    float xtv[2];
    if (wg == 0) {
#pragma unroll
        for (int e = 0; e < 2; e++) xtv[e] = __ldcg(&g_xT[0 * BATCH + b0 + rows[e]]);
    }

    for (int n = 0; n <= SEQT; n++) {
        const uint32_t rbase = sbA + (uint32_t)(n & 1) * ABYTES;         // read parity
        const uint32_t wpar  = (uint32_t)((n + 1) & 1) * ABYTES;         // write parity offset

        // wait pairs with previous iteration's arrive (n=0 covered by setup sync)
        if (n > 0) CLUSTER_WAIT();

        if (wg == 0) {
            // ===== layer 1: gates1(t=n) = h1(n-1) @ Whh1^T =====
            if (n < SEQT) {
                float acc[4][2][4];
#pragma unroll
                for (int a1 = 0; a1 < 4; a1++)
#pragma unroll
                    for (int a2 = 0; a2 < 2; a2++)
#pragma unroll
                        for (int a3 = 0; a3 < 4; a3++) acc[a1][a2][a3] = 0.f;

#pragma unroll
                for (int ktp = 0; ktp < 8; ktp++) {
                    uint32_t af[4];
                    ldmA(af, rbase + lmoff + ktp * 32u);
                    mmaf16(acc[0][0], af, bh[ktp * 4 + 0].x, bh[ktp * 4 + 0].y);
                    mmaf16(acc[1][0], af, bh[ktp * 4 + 0].z, bh[ktp * 4 + 0].w);
                    mmaf16(acc[2][0], af, bh[ktp * 4 + 1].x, bh[ktp * 4 + 1].y);
                    mmaf16(acc[3][0], af, bh[ktp * 4 + 1].z, bh[ktp * 4 + 1].w);
                    mmaf16(acc[0][1], af, bh[ktp * 4 + 2].x, bh[ktp * 4 + 2].y);
                    mmaf16(acc[1][1], af, bh[ktp * 4 + 2].z, bh[ktp * 4 + 2].w);
                    mmaf16(acc[2][1], af, bh[ktp * 4 + 3].x, bh[ktp * 4 + 3].y);
                    mmaf16(acc[3][1], af, bh[ktp * 4 + 3].z, bh[ktp * 4 + 3].w);
                }
#pragma unroll
                for (int e = 0; e < 2; e++)
#pragma unroll
                    for (int q2 = 0; q2 < 2; q2++) {
                        float hv[2];
#pragma unroll
                        for (int qq = 0; qq < 2; qq++) {
                            int fr = e * 2 + qq;
                            int ii = q2 * 2 + qq;
                            float gi = acc[0][q2][fr] + xtv[e] * wxv[ii]      + bbv[ii];
                            float gf = acc[1][q2][fr] + xtv[e] * wxv[4 + ii]  + bbv[4 + ii];
                            float gg = acc[2][q2][fr] + xtv[e] * wxv[8 + ii]  + bbv[8 + ii];
                            float go = acc[3][q2][fr] + xtv[e] * wxv[12 + ii] + bbv[12 + ii];
                            float iv = sigfa(gi), fv = sigfa(gf), gv = tanha(gg), ov = sigfa(go);
                            int ci = e * 4 + q2 * 2 + qq;
                            cc[ci] = fv * cc[ci] + iv * gv;
                            hv[qq] = ov * tanha(cc[ci]);
                        }
                        __half2 hp = __floats2half2_rn(hv[0], hv[1]);
                        uint32_t v = *(uint32_t*)&hp;
                        uint32_t boff = wpar + (uint32_t)(rows[e] * SAW + wcol + q2 * 4) * 4u;
                        STSL(sbA + boff, v);
                        STSC(dstPeer + boff, v);
                    }
            }
        } else {
            // ===== layer 2: gates2(t=n-1) = [h1(n-1)|h2(n-2)] @ [Wih2|Whh2]^T =====
            if (n > 0) {
                float acc[4][2][4];
#pragma unroll
                for (int a1 = 0; a1 < 4; a1++)
#pragma unroll
                    for (int a2 = 0; a2 < 2; a2++)
#pragma unroll
                        for (int a3 = 0; a3 < 4; a3++) acc[a1][a2][a3] = 0.f;

                // ktp 0..7 from hoisted regs
#pragma unroll
                for (int ktp = 0; ktp < 8; ktp++) {
                    uint32_t af[4];
                    ldmA(af, rbase + lmoff + ktp * 32u);
                    mmaf16(acc[0][0], af, bh[ktp * 4 + 0].x, bh[ktp * 4 + 0].y);
                    mmaf16(acc[1][0], af, bh[ktp * 4 + 0].z, bh[ktp * 4 + 0].w);
                    mmaf16(acc[2][0], af, bh[ktp * 4 + 1].x, bh[ktp * 4 + 1].y);
                    mmaf16(acc[3][0], af, bh[ktp * 4 + 1].z, bh[ktp * 4 + 1].w);
                    mmaf16(acc[0][1], af, bh[ktp * 4 + 2].x, bh[ktp * 4 + 2].y);
                    mmaf16(acc[1][1], af, bh[ktp * 4 + 2].z, bh[ktp * 4 + 2].w);
                    mmaf16(acc[2][1], af, bh[ktp * 4 + 3].x, bh[ktp * 4 + 3].y);
                    mmaf16(acc[3][1], af, bh[ktp * 4 + 3].z, bh[ktp * 4 + 3].w);
                }
                // ktp 8..15 from smem
#pragma unroll 2
                for (int ktp = 8; ktp < 16; ktp++) {
                    int base = (lwid * 2) * 16 + ktp;
                    uint4 b0v = Bq2[((base) * 2 + 0) * 32 + lane];
                    uint4 b1v = Bq2[((base) * 2 + 1) * 32 + lane];
                    uint4 b2v = Bq2[((base + 16) * 2 + 0) * 32 + lane];
                    uint4 b3v = Bq2[((base + 16) * 2 + 1) * 32 + lane];
                    uint32_t af[4];
                    ldmA(af, rbase + lmoff + ktp * 32u);
                    mmaf16(acc[0][0], af, b0v.x, b0v.y);
                    mmaf16(acc[1][0], af, b0v.z, b0v.w);
                    mmaf16(acc[2][0], af, b1v.x, b1v.y);
                    mmaf16(acc[3][0], af, b1v.z, b1v.w);
                    mmaf16(acc[0][1], af, b2v.x, b2v.y);
                    mmaf16(acc[1][1], af, b2v.z, b2v.w);
                    mmaf16(acc[2][1], af, b3v.x, b3v.y);
                    mmaf16(acc[3][1], af, b3v.z, b3v.w);
                }
#pragma unroll
                for (int e = 0; e < 2; e++)
#pragma unroll
                    for (int q2 = 0; q2 < 2; q2++) {
                        float hv[2];
#pragma unroll
                        for (int qq = 0; qq < 2; qq++) {
                            int fr = e * 2 + qq;
                            int ii = q2 * 2 + qq;
                            float gi = acc[0][q2][fr] + bbv[ii];
                            float gf = acc[1][q2][fr] + bbv[4 + ii];
                            float gg = acc[2][q2][fr] + bbv[8 + ii];
                            float go = acc[3][q2][fr] + bbv[12 + ii];
                            float iv = sigfa(gi), fv = sigfa(gf), gv = tanha(gg), ov = sigfa(go);
                            int ci = e * 4 + q2 * 2 + qq;
                            cc[ci] = fv * cc[ci] + iv * gv;
                            hv[qq] = ov * tanha(cc[ci]);
                        }
                        __half2 hp = __floats2half2_rn(hv[0], hv[1]);
                        uint32_t v = *(uint32_t*)&hp;
                        uint32_t boff = wpar + (uint32_t)(rows[e] * SAW + 64 + wcol + q2 * 4) * 4u;
                        STSL(sbA + boff, v);
                        STSC(dstPeer + boff, v);
                    }
            }
            // n == 0: h2(-1) = 0 already in pre-zeroed buffers
        }

        // release this iteration's stores; overlap the barrier with x prefetch
        CLUSTER_ARRIVE();
        if (wg == 0 && n + 1 < SEQT) {
#pragma unroll
            for (int e = 0; e < 2; e++) xtv[e] = __ldcg(&g_xT[(n + 1) * BATCH + b0 + rows[e]]);
        }
    }

    // final wait pairs with last iteration's arrive; then h2 halves from peer are visible
    CLUSTER_WAIT();

    // ---- final linear: out[b] = h2[b,:] . Wl + bl ----
    // h2(SEQT-1) sits in A buffer parity (SEQT+1)&1, words 64..127 of each row (local smem)
    if (rank == 0 && tid < MROWS) {
        const uint32_t* hr = sm + OF_A + ((SEQT + 1) & 1) * AWORDS + tid * SAW + 64;
        float acc = bl[0];
#pragma unroll 16
        for (int w = 0; w < 64; w++) {
            uint32_t u = hr[w];
            float2 f = __half22float2(*(__half2*)&u);
            acc += f.x * Wl[2 * w] + f.y * Wl[2 * w + 1];
        }
        out[b0 + tid] = acc;
    }
    // keep both CTAs resident until peer reads of DSMEM are impossible
    CLUSTER_ARRIVE();
    CLUSTER_WAIT();
}

// ======================= launch =======================
extern "C" void kernel_launch(void* const* d_in, const int* in_sizes, int n_in,
                              void* d_out, int out_size) {
    const float* x    = (const float*)d_in[0];
    const float* Wih1 = (const float*)d_in[1];
    const float* Whh1 = (const float*)d_in[2];
    const float* bih1 = (const float*)d_in[3];
    const float* bhh1 = (const float*)d_in[4];
    const float* Wih2 = (const float*)d_in[5];
    const float* Whh2 = (const float*)d_in[6];
    const float* bih2 = (const float*)d_in[7];
    const float* bhh2 = (const float*)d_in[8];
    const float* Wl   = (const float*)d_in[9];
    const float* bl   = (const float*)d_in[10];
    float* out = (float*)d_out;

    cudaFuncSetAttribute(lstm2_kernel, cudaFuncAttributeMaxDynamicSharedMemorySize, SMEM_BYTES);

    xT_kernel<<<(BATCH * SEQT + 255) / 256, 256>>>(x);
    lstm2_kernel<<<(BATCH / MROWS) * CL, NTHREADS, SMEM_BYTES>>>(
        Wih1, Whh1, bih1, bhh1, Wih2, Whh2, bih2, bhh2, Wl, bl, out);
}

// round 16
// speedup vs baseline: 4.3451x; 1.1150x over previous
#include <cuda_runtime.h>
#include <cuda_fp16.h>
#include <cstdint>

#define HN       128
#define BATCH    1024
#define SEQT     512
#define CL       2            // CTAs per cluster
#define MROWS    16           // batch rows per cluster
#define NTHREADS 256

#define SAW      132          // A-tile row stride in 32-bit words (264 fp16 = 528 B)
#define AWORDS   (MROWS * SAW)           // 2112 words per A buffer
#define ABYTES   (AWORDS * 4)            // 8448 B

// ---- shared memory layout (32-bit word offsets) ----
#define OF_A     0                       // A tiles x2 (parity) = 4224 words
#define OF_B1    (2 * AWORDS)            // layer-1 B frags: 16384 words (64 KB)
#define OF_B2    (OF_B1 + 16384)         // layer-2 B frags: 32768 words (128 KB)
#define OF_WX    (OF_B2 + 32768)         // Wih1 slice   [256] floats (4 gates x 64 dims)
#define OF_BB1   (OF_WX + 256)           // bih1+bhh1    [256] floats
#define OF_BB2   (OF_BB1 + 256)          // bih2+bhh2    [256] floats
#define OF_P     (OF_BB2 + 256)          // layer-2 partial (fp16x2): 16 x 128 words = 8 KB
#define SMEM_WORDS (OF_P + 2048)
#define SMEM_BYTES (SMEM_WORDS * 4)      // 224,768 B

// ---- device scratch (allocation-free) ----
__device__ float g_xT[SEQT * BATCH];     // x transposed to [T, B]

// ======================= helpers =======================
__device__ __forceinline__ uint32_t smem_u32(const void* p) {
    uint32_t a;
    asm("{ .reg .u64 t; cvta.to.shared.u64 t, %1; cvt.u32.u64 %0, t; }" : "=r"(a) : "l"(p));
    return a;
}
__device__ __forceinline__ uint32_t mapa_u32(uint32_t addr, int r) {
    uint32_t o;
    asm("mapa.shared::cluster.u32 %0, %1, %2;" : "=r"(o) : "r"(addr), "r"(r));
    return o;
}
#define CLUSTER_ARRIVE() asm volatile("barrier.cluster.arrive.aligned;" ::: "memory")
#define CLUSTER_WAIT()   asm volatile("barrier.cluster.wait.aligned;" ::: "memory")
#define STSC(addr, v)    asm volatile("st.shared::cluster.u32 [%0], %1;" :: "r"(addr), "r"(v) : "memory")
#define STSL(addr, v)    asm volatile("st.shared.u32 [%0], %1;" :: "r"(addr), "r"(v) : "memory")
#define BAR_ARRIVE(id)   asm volatile("bar.arrive %0, %1;" :: "r"(id), "r"(256) : "memory")
#define BAR_SYNC(id)     asm volatile("bar.sync %0, %1;"   :: "r"(id), "r"(256) : "memory")

__device__ __forceinline__ void mmaf16(float* d, const uint32_t* a, uint32_t b0, uint32_t b1) {
    asm volatile(
        "mma.sync.aligned.m16n8k16.row.col.f32.f16.f16.f32 "
        "{%0,%1,%2,%3}, {%4,%5,%6,%7}, {%8,%9}, {%0,%1,%2,%3};"
        : "+f"(d[0]), "+f"(d[1]), "+f"(d[2]), "+f"(d[3])
        : "r"(a[0]), "r"(a[1]), "r"(a[2]), "r"(a[3]), "r"(b0), "r"(b1));
}
__device__ __forceinline__ void ldmA(uint32_t* r, uint32_t addr) {
    asm volatile("ldmatrix.sync.aligned.m8n8.x4.shared.b16 {%0,%1,%2,%3}, [%4];"
                 : "=r"(r[0]), "=r"(r[1]), "=r"(r[2]), "=r"(r[3]) : "r"(addr));
}
// full-approx activations (validated: rel_err 4.64e-4)
__device__ __forceinline__ float tanha(float x) {
    float y; asm("tanh.approx.f32 %0, %1;" : "=f"(y) : "f"(x)); return y;
}
__device__ __forceinline__ float sigfa(float x) {
    return fmaf(0.5f, tanha(0.5f * x), 0.5f);
}

// ======================= kernels =======================
__global__ void xT_kernel(const float* __restrict__ x) {
    int i = blockIdx.x * blockDim.x + threadIdx.x;   // i = t*1024 + b (coalesced writes)
    if (i < BATCH * SEQT) {
        int tt = i >> 10, b = i & 1023;
        g_xT[i] = x[b * SEQT + tt];
    }
}

extern "C" __global__ void __launch_bounds__(NTHREADS, 1) __cluster_dims__(CL, 1, 1)
lstm2_kernel(const float* __restrict__ Wih1, const float* __restrict__ Whh1,
             const float* __restrict__ bih1, const float* __restrict__ bhh1,
             const float* __restrict__ Wih2, const float* __restrict__ Whh2,
             const float* __restrict__ bih2, const float* __restrict__ bhh2,
             const float* __restrict__ Wl,   const float* __restrict__ bl,
             float* __restrict__ out)
{
    extern __shared__ uint32_t sm[];
    const int tid  = threadIdx.x;
    const int lane = tid & 31;
    const int wid  = tid >> 5;          // 0..7
    const int wg   = wid >> 2;          // 0 = layer-1 (+L2 partial), 1 = layer-2 group
    const int lwid = wid & 3;           // warp within group -> 16-dim slice
    const int g    = lane >> 2;
    const int tq   = lane & 3;
    const int rank = blockIdx.x & (CL - 1);
    const int b0   = (blockIdx.x / CL) * MROWS;

    float* WX  = (float*)(sm + OF_WX);
    float* BB1 = (float*)(sm + OF_BB1);
    float* BB2 = (float*)(sm + OF_BB2);

    // ---- pack weight slices into fp16 mma-fragment order (same as R15) ----
    for (int idx = tid; idx < 16384; idx += NTHREADS) {         // layer 1 (K=128, KTP=8)
        int j = idx & 3, ln = (idx >> 2) & 31, p = (idx >> 7) & 1;
        int ktp = (idx >> 8) & 7, q2 = (idx >> 11) & 1, w = idx >> 12;
        int gate = p * 2 + (j >> 1), reg = j & 1;
        int k0 = ktp * 16 + reg * 8 + 2 * (ln & 3);
        int dim = w * 16 + q2 * 8 + (ln >> 2);
        int gr = gate * HN + rank * 64 + dim;
        __half2 hv = __floats2half2_rn(Whh1[gr * HN + k0], Whh1[gr * HN + k0 + 1]);
        sm[OF_B1 + idx] = *(uint32_t*)&hv;
    }
    for (int idx = tid; idx < 32768; idx += NTHREADS) {         // layer 2 (K=256, KTP=16)
        int j = idx & 3, ln = (idx >> 2) & 31, p = (idx >> 7) & 1;
        int ktp = (idx >> 8) & 15, q2 = (idx >> 12) & 1, w = idx >> 13;
        int gate = p * 2 + (j >> 1), reg = j & 1;
        int k0 = ktp * 16 + reg * 8 + 2 * (ln & 3);
        int dim = w * 16 + q2 * 8 + (ln >> 2);
        int gr = gate * HN + rank * 64 + dim;
        float w0 = (k0 < HN)     ? Wih2[gr * HN + k0]     : Whh2[gr * HN + k0 - HN];
        float w1 = (k0 + 1 < HN) ? Wih2[gr * HN + k0 + 1] : Whh2[gr * HN + k0 + 1 - HN];
        __half2 hv = __floats2half2_rn(w0, w1);
        sm[OF_B2 + idx] = *(uint32_t*)&hv;
    }
    {   // WX / biases: 4 gates x 64 dims
        int gt = tid >> 6, q = tid & 63;
        int gr = gt * HN + rank * 64 + q;
        WX[tid]  = Wih1[gr];
        BB1[tid] = bih1[gr] + bhh1[gr];
        BB2[tid] = bih2[gr] + bhh2[gr];
    }
    for (int i = tid; i < 2 * AWORDS; i += NTHREADS) sm[OF_A + i] = 0u;   // both parities zero
    __syncthreads();
    // publish zeroed A-tiles + weights before any peer DSMEM write/read
    CLUSTER_ARRIVE();
    CLUSTER_WAIT();

    // per-thread rows (2) and ldmatrix offset (single M16 tile)
    int rows[2];
    rows[0] = g;
    rows[1] = g + 8;

    const uint32_t sbA = smem_u32(sm) + OF_A * 4;
    const uint32_t lmoff = (uint32_t)(lane & 15) * 528u + ((lane >> 4) & 1) * 16u;
    // DSMEM write base: peer CTA's A-tile only (local goes via plain STS)
    const uint32_t dstPeer = mapa_u32(sbA, rank ^ 1);

    const uint4* Bq1 = (const uint4*)(sm + OF_B1);
    const uint4* Bq2 = (const uint4*)(sm + OF_B2);

    // ---- hoist loop-invariant B fragments into registers ----
    // WG0: layer-1 all 8 ktp. WG1: layer-2 ktp 0..7. (rest from smem)
    uint4 bh[32];
    if (wg == 0) {
#pragma unroll
        for (int ktp = 0; ktp < 8; ktp++) {
            int base = (lwid * 2) * 8 + ktp;
            bh[ktp * 4 + 0] = Bq1[((base) * 2 + 0) * 32 + lane];
            bh[ktp * 4 + 1] = Bq1[((base) * 2 + 1) * 32 + lane];
            bh[ktp * 4 + 2] = Bq1[((base + 8) * 2 + 0) * 32 + lane];
            bh[ktp * 4 + 3] = Bq1[((base + 8) * 2 + 1) * 32 + lane];
        }
    } else {
#pragma unroll
        for (int ktp = 0; ktp < 8; ktp++) {
            int base = (lwid * 2) * 16 + ktp;
            bh[ktp * 4 + 0] = Bq2[((base) * 2 + 0) * 32 + lane];
            bh[ktp * 4 + 1] = Bq2[((base) * 2 + 1) * 32 + lane];
            bh[ktp * 4 + 2] = Bq2[((base + 16) * 2 + 0) * 32 + lane];
            bh[ktp * 4 + 3] = Bq2[((base + 16) * 2 + 1) * 32 + lane];
        }
    }
    // ---- hoist epilogue constants (per-thread slice of WX / biases) ----
    float wxv[16], bbv[16];
    {
        const float* Bt = (wg == 0) ? BB1 : BB2;
#pragma unroll
        for (int gate = 0; gate < 4; gate++)
#pragma unroll
            for (int q2 = 0; q2 < 2; q2++)
#pragma unroll
                for (int qq = 0; qq < 2; qq++) {
                    int qloc = lwid * 16 + q2 * 8 + tq * 2 + qq;
                    int ii = gate * 4 + q2 * 2 + qq;
                    bbv[ii] = Bt[gate * 64 + qloc];
                    wxv[ii] = (wg == 0) ? WX[gate * 64 + qloc] : 0.f;
                }
    }

    // WG0 carries c1, WG1 carries c2: 8 cells (2 rows x 2 q2 x 2 qq)
    float cc[8];
#pragma unroll
    for (int i = 0; i < 8; i++) cc[i] = 0.f;

    // write word-column (within 128-word row): h1 -> +0, h2 -> +64
    const int wcol = rank * 32 + lwid * 8 + tq;    // + q2*4 added in loop

    // initial x prefetch (t=0)
    float xtv[2];
    if (wg == 0) {
#pragma unroll
        for (int e = 0; e < 2; e++) xtv[e] = __ldcg(&g_xT[0 * BATCH + b0 + rows[e]]);
    } else {
        // prime WAR barrier (id 2): WG0's first bar.sync(2) consumes this
        BAR_ARRIVE(2);
    }

    for (int n = 0; n <= SEQT; n++) {
        const uint32_t rbase = sbA + (uint32_t)(n & 1) * ABYTES;         // read parity
        const uint32_t wpar  = (uint32_t)((n + 1) & 1) * ABYTES;         // write parity offset

        // wait pairs with previous iteration's arrive (n=0 covered by setup sync)
        if (n > 0) CLUSTER_WAIT();

        if (wg == 0) {
            // ---- layer-2 partial: ktp 12..15 (computed first, handed to WG1) ----
            BAR_SYNC(2);     // WG1 finished reading previous partial
            {
                float acc[4][2][4];
#pragma unroll
                for (int a1 = 0; a1 < 4; a1++)
#pragma unroll
                    for (int a2 = 0; a2 < 2; a2++)
#pragma unroll
                        for (int a3 = 0; a3 < 4; a3++) acc[a1][a2][a3] = 0.f;
#pragma unroll
                for (int ktp = 12; ktp < 16; ktp++) {
                    int base = (lwid * 2) * 16 + ktp;
                    uint4 b0v = Bq2[((base) * 2 + 0) * 32 + lane];
                    uint4 b1v = Bq2[((base) * 2 + 1) * 32 + lane];
                    uint4 b2v = Bq2[((base + 16) * 2 + 0) * 32 + lane];
                    uint4 b3v = Bq2[((base + 16) * 2 + 1) * 32 + lane];
                    uint32_t af[4];
                    ldmA(af, rbase + lmoff + ktp * 32u);
                    mmaf16(acc[0][0], af, b0v.x, b0v.y);
                    mmaf16(acc[1][0], af, b0v.z, b0v.w);
                    mmaf16(acc[2][0], af, b1v.x, b1v.y);
                    mmaf16(acc[3][0], af, b1v.z, b1v.w);
                    mmaf16(acc[0][1], af, b2v.x, b2v.y);
                    mmaf16(acc[1][1], af, b2v.z, b2v.w);
                    mmaf16(acc[2][1], af, b3v.x, b3v.y);
                    mmaf16(acc[3][1], af, b3v.z, b3v.w);
                }
                // store partial as fp16x2, layout [idx][tid] (conflict-free)
#pragma unroll
                for (int gate = 0; gate < 4; gate++)
#pragma unroll
                    for (int q2 = 0; q2 < 2; q2++)
#pragma unroll
                        for (int e = 0; e < 2; e++) {
                            __half2 hp = __floats2half2_rn(acc[gate][q2][e * 2 + 0],
                                                           acc[gate][q2][e * 2 + 1]);
                            sm[OF_P + (gate * 4 + q2 * 2 + e) * 128 + tid] = *(uint32_t*)&hp;
                        }
            }
            BAR_ARRIVE(1);   // partial ready for WG1

            // ===== layer 1: gates1(t=n) = h1(n-1) @ Whh1^T =====
            if (n < SEQT) {
                float acc[4][2][4];
#pragma unroll
                for (int a1 = 0; a1 < 4; a1++)
#pragma unroll
                    for (int a2 = 0; a2 < 2; a2++)
#pragma unroll
                        for (int a3 = 0; a3 < 4; a3++) acc[a1][a2][a3] = 0.f;
#pragma unroll
                for (int ktp = 0; ktp < 8; ktp++) {
                    uint32_t af[4];
                    ldmA(af, rbase + lmoff + ktp * 32u);
                    mmaf16(acc[0][0], af, bh[ktp * 4 + 0].x, bh[ktp * 4 + 0].y);
                    mmaf16(acc[1][0], af, bh[ktp * 4 + 0].z, bh[ktp * 4 + 0].w);
                    mmaf16(acc[2][0], af, bh[ktp * 4 + 1].x, bh[ktp * 4 + 1].y);
                    mmaf16(acc[3][0], af, bh[ktp * 4 + 1].z, bh[ktp * 4 + 1].w);
                    mmaf16(acc[0][1], af, bh[ktp * 4 + 2].x, bh[ktp * 4 + 2].y);
                    mmaf16(acc[1][1], af, bh[ktp * 4 + 2].z, bh[ktp * 4 + 2].w);
                    mmaf16(acc[2][1], af, bh[ktp * 4 + 3].x, bh[ktp * 4 + 3].y);
                    mmaf16(acc[3][1], af, bh[ktp * 4 + 3].z, bh[ktp * 4 + 3].w);
                }
#pragma unroll
                for (int e = 0; e < 2; e++)
#pragma unroll
                    for (int q2 = 0; q2 < 2; q2++) {
                        float hv[2];
#pragma unroll
                        for (int qq = 0; qq < 2; qq++) {
                            int fr = e * 2 + qq;
                            int ii = q2 * 2 + qq;
                            float gi = acc[0][q2][fr] + xtv[e] * wxv[ii]      + bbv[ii];
                            float gf = acc[1][q2][fr] + xtv[e] * wxv[4 + ii]  + bbv[4 + ii];
                            float gg = acc[2][q2][fr] + xtv[e] * wxv[8 + ii]  + bbv[8 + ii];
                            float go = acc[3][q2][fr] + xtv[e] * wxv[12 + ii] + bbv[12 + ii];
                            float iv = sigfa(gi), fv = sigfa(gf), gv = tanha(gg), ov = sigfa(go);
                            int ci = e * 4 + q2 * 2 + qq;
                            cc[ci] = fv * cc[ci] + iv * gv;
                            hv[qq] = ov * tanha(cc[ci]);
                        }
                        __half2 hp = __floats2half2_rn(hv[0], hv[1]);
                        uint32_t v = *(uint32_t*)&hp;
                        uint32_t boff = wpar + (uint32_t)(rows[e] * SAW + wcol + q2 * 4) * 4u;
                        STSL(sbA + boff, v);
                        STSC(dstPeer + boff, v);
                    }
            }
        } else {
            // ===== layer 2: gates2(t=n-1), ktp 0..11 (WG0 supplies 12..15) =====
            float acc[4][2][4];
            if (n > 0) {
#pragma unroll
                for (int a1 = 0; a1 < 4; a1++)
#pragma unroll
                    for (int a2 = 0; a2 < 2; a2++)
#pragma unroll
                        for (int a3 = 0; a3 < 4; a3++) acc[a1][a2][a3] = 0.f;
                // ktp 0..7 hoisted
#pragma unroll
                for (int ktp = 0; ktp < 8; ktp++) {
                    uint32_t af[4];
                    ldmA(af, rbase + lmoff + ktp * 32u);
                    mmaf16(acc[0][0], af, bh[ktp * 4 + 0].x, bh[ktp * 4 + 0].y);
                    mmaf16(acc[1][0], af, bh[ktp * 4 + 0].z, bh[ktp * 4 + 0].w);
                    mmaf16(acc[2][0], af, bh[ktp * 4 + 1].x, bh[ktp * 4 + 1].y);
                    mmaf16(acc[3][0], af, bh[ktp * 4 + 1].z, bh[ktp * 4 + 1].w);
                    mmaf16(acc[0][1], af, bh[ktp * 4 + 2].x, bh[ktp * 4 + 2].y);
                    mmaf16(acc[1][1], af, bh[ktp * 4 + 2].z, bh[ktp * 4 + 2].w);
                    mmaf16(acc[2][1], af, bh[ktp * 4 + 3].x, bh[ktp * 4 + 3].y);
                    mmaf16(acc[3][1], af, bh[ktp * 4 + 3].z, bh[ktp * 4 + 3].w);
                }
                // ktp 8..11 from smem
#pragma unroll 2
                for (int ktp = 8; ktp < 12; ktp++) {
                    int base = (lwid * 2) * 16 + ktp;
                    uint4 b0v = Bq2[((base) * 2 + 0) * 32 + lane];
                    uint4 b1v = Bq2[((base) * 2 + 1) * 32 + lane];
                    uint4 b2v = Bq2[((base + 16) * 2 + 0) * 32 + lane];
                    uint4 b3v = Bq2[((base + 16) * 2 + 1) * 32 + lane];
                    uint32_t af[4];
                    ldmA(af, rbase + lmoff + ktp * 32u);
                    mmaf16(acc[0][0], af, b0v.x, b0v.y);
                    mmaf16(acc[1][0], af, b0v.z, b0v.w);
                    mmaf16(acc[2][0], af, b1v.x, b1v.y);
                    mmaf16(acc[3][0], af, b1v.z, b1v.w);
                    mmaf16(acc[0][1], af, b2v.x, b2v.y);
                    mmaf16(acc[1][1], af, b2v.z, b2v.w);
                    mmaf16(acc[2][1], af, b3v.x, b3v.y);
                    mmaf16(acc[3][1], af, b3v.z, b3v.w);
                }
            }
            BAR_SYNC(1);     // wait for WG0's partial
            if (n > 0) {
                int pt = tid - 128;
#pragma unroll
                for (int gate = 0; gate < 4; gate++)
#pragma unroll
                    for (int q2 = 0; q2 < 2; q2++)
#pragma unroll
                        for (int e = 0; e < 2; e++) {
                            uint32_t u = sm[OF_P + (gate * 4 + q2 * 2 + e) * 128 + pt];
                            float2 f = __half22float2(*(__half2*)&u);
                            acc[gate][q2][e * 2 + 0] += f.x;
                            acc[gate][q2][e * 2 + 1] += f.y;
                        }
#pragma unroll
                for (int e = 0; e < 2; e++)
#pragma unroll
                    for (int q2 = 0; q2 < 2; q2++) {
                        float hv[2];
#pragma unroll
                        for (int qq = 0; qq < 2; qq++) {
                            int fr = e * 2 + qq;
                            int ii = q2 * 2 + qq;
                            float gi = acc[0][q2][fr] + bbv[ii];
                            float gf = acc[1][q2][fr] + bbv[4 + ii];
                            float gg = acc[2][q2][fr] + bbv[8 + ii];
                            float go = acc[3][q2][fr] + bbv[12 + ii];
                            float iv = sigfa(gi), fv = sigfa(gf), gv = tanha(gg), ov = sigfa(go);
                            int ci = e * 4 + q2 * 2 + qq;
                            cc[ci] = fv * cc[ci] + iv * gv;
                            hv[qq] = ov * tanha(cc[ci]);
                        }
                        __half2 hp = __floats2half2_rn(hv[0], hv[1]);
                        uint32_t v = *(uint32_t*)&hp;
                        uint32_t boff = wpar + (uint32_t)(rows[e] * SAW + 64 + wcol + q2 * 4) * 4u;
                        STSL(sbA + boff, v);
                        STSC(dstPeer + boff, v);
                    }
            }
            BAR_ARRIVE(2);   // done reading partial; WG0 may overwrite next iter
            // n == 0: h2(-1) = 0 already in pre-zeroed buffers
        }

        // release this iteration's stores; overlap the barrier with x prefetch
        CLUSTER_ARRIVE();
        if (wg == 0 && n + 1 < SEQT) {
#pragma unroll
            for (int e = 0; e < 2; e++) xtv[e] = __ldcg(&g_xT[(n + 1) * BATCH + b0 + rows[e]]);
        }
    }

    // final wait pairs with last iteration's arrive; then h2 halves from peer are visible
    CLUSTER_WAIT();

    // ---- final linear: out[b] = h2[b,:] . Wl + bl ----
    // h2(SEQT-1) sits in A buffer parity (SEQT+1)&1, words 64..127 of each row (local smem)
    if (rank == 0 && tid < MROWS) {
        const uint32_t* hr = sm + OF_A + ((SEQT + 1) & 1) * AWORDS + tid * SAW + 64;
        float acc = bl[0];
#pragma unroll 16
        for (int w = 0; w < 64; w++) {
            uint32_t u = hr[w];
            float2 f = __half22float2(*(__half2*)&u);
            acc += f.x * Wl[2 * w] + f.y * Wl[2 * w + 1];
        }
        out[b0 + tid] = acc;
    }
    // keep both CTAs resident until peer reads of DSMEM are impossible
    CLUSTER_ARRIVE();
    CLUSTER_WAIT();
}

// ======================= launch =======================
extern "C" void kernel_launch(void* const* d_in, const int* in_sizes, int n_in,
                              void* d_out, int out_size) {
    const float* x    = (const float*)d_in[0];
    const float* Wih1 = (const float*)d_in[1];
    const float* Whh1 = (const float*)d_in[2];
    const float* bih1 = (const float*)d_in[3];
    const float* bhh1 = (const float*)d_in[4];
    const float* Wih2 = (const float*)d_in[5];
    const float* Whh2 = (const float*)d_in[6];
    const float* bih2 = (const float*)d_in[7];
    const float* bhh2 = (const float*)d_in[8];
    const float* Wl   = (const float*)d_in[9];
    const float* bl   = (const float*)d_in[10];
    float* out = (float*)d_out;

    cudaFuncSetAttribute(lstm2_kernel, cudaFuncAttributeMaxDynamicSharedMemorySize, SMEM_BYTES);

    xT_kernel<<<(BATCH * SEQT + 255) / 256, 256>>>(x);
    lstm2_kernel<<<(BATCH / MROWS) * CL, NTHREADS, SMEM_BYTES>>>(
        Wih1, Whh1, bih1, bhh1, Wih2, Whh2, bih2, bhh2, Wl, bl, out);
}